// round 12
// baseline (speedup 1.0000x reference)
#include <cuda_runtime.h>
#include <cuda_bf16.h>
#include <math.h>
#include <stdint.h>

#define BATCH  4
#define SEQ    2048
#define EMBED  256
#define HIDDEN 512
#define ROWS   (BATCH * SEQ)   // 8192

// -------- scratch (allocation-free: __device__ globals) --------
__device__ __align__(16) __nv_bfloat16 g_acth[ROWS * HIDDEN];            // 8 MB
__device__ __align__(16) __nv_bfloat16 g_actl[ROWS * HIDDEN];
__device__ __align__(16) __nv_bfloat16 g_wth[3 * HIDDEN * HIDDEN];       // W^T hi  [z][n][k]
__device__ __align__(16) __nv_bfloat16 g_wtl[3 * HIDDEN * HIDDEN];
__device__ __align__(16) __nv_bfloat16 g_qh[ROWS * HIDDEN];
__device__ __align__(16) __nv_bfloat16 g_ql[ROWS * HIDDEN];
__device__ __align__(16) __nv_bfloat16 g_kh[ROWS * HIDDEN];
__device__ __align__(16) __nv_bfloat16 g_kl[ROWS * HIDDEN];
__device__ __align__(16) __nv_bfloat16 g_vth[BATCH * HIDDEN * SEQ];      // V^T [b][h][s]
__device__ __align__(16) __nv_bfloat16 g_vtl[BATCH * HIDDEN * SEQ];
__device__ float g_scores[(size_t)BATCH * SEQ * SEQ];                    // 64 MB
__device__ __align__(16) __nv_bfloat16 g_ah[(size_t)BATCH * SEQ * SEQ];  // attn hi
__device__ __align__(16) __nv_bfloat16 g_al[(size_t)BATCH * SEQ * SEQ];  // attn lo

__device__ __forceinline__ void bf16_split(float x, __nv_bfloat16& h, __nv_bfloat16& l) {
    h = __float2bfloat16_rn(x);
    l = __float2bfloat16_rn(x - __bfloat162float(h));
}

// ============================================================
// Kernel 1: act = gelu( emb_table[tok] @ W1 + b1 )  (fp32 SIMT, epi -> bf16 hi/lo)
// ============================================================
__global__ void embed_mlp_kernel(const int* __restrict__ tok,
                                 const float* __restrict__ emb,
                                 const float* __restrict__ W1,
                                 const float* __restrict__ b1)
{
    __shared__ float As[64][17];
    __shared__ float Bs[16][64];

    const int tile_n = blockIdx.x * 64;
    const int tile_m = blockIdx.y * 64;
    const int t  = threadIdx.x;
    const int tx = t & 15;
    const int ty = t >> 4;

    float acc[4][4] = {};

    for (int k0 = 0; k0 < EMBED; k0 += 16) {
        #pragma unroll
        for (int i = 0; i < 4; i++) {
            int idx = t + i * 256;
            int r = idx >> 4, c = idx & 15;
            int token = tok[tile_m + r];
            As[r][c] = emb[(size_t)token * EMBED + k0 + c];
        }
        #pragma unroll
        for (int i = 0; i < 4; i++) {
            int idx = t + i * 256;
            int r = idx >> 6, c = idx & 63;
            Bs[r][c] = W1[(k0 + r) * HIDDEN + tile_n + c];
        }
        __syncthreads();
        #pragma unroll
        for (int kk = 0; kk < 16; kk++) {
            float a[4], b[4];
            #pragma unroll
            for (int i = 0; i < 4; i++) a[i] = As[ty * 4 + i][kk];
            #pragma unroll
            for (int j = 0; j < 4; j++) b[j] = Bs[kk][tx * 4 + j];
            #pragma unroll
            for (int i = 0; i < 4; i++)
                #pragma unroll
                for (int j = 0; j < 4; j++)
                    acc[i][j] = fmaf(a[i], b[j], acc[i][j]);
        }
        __syncthreads();
    }

    #pragma unroll
    for (int i = 0; i < 4; i++) {
        int row = tile_m + ty * 4 + i;
        #pragma unroll
        for (int j = 0; j < 4; j++) {
            int col = tile_n + tx * 4 + j;
            float x = acc[i][j] + b1[col];
            float g = 0.5f * x * (1.0f + erff(x * 0.7071067811865475f));
            __nv_bfloat16 h, l;
            bf16_split(g, h, l);
            size_t o = (size_t)row * HIDDEN + col;
            g_acth[o] = h; g_actl[o] = l;
        }
    }
}

// ============================================================
// Kernel 1b: transpose + hi/lo split of Wq/Wk/Wv -> g_wt{h,l}[z][n][k]
// ============================================================
__global__ void wsplit_kernel(const float* __restrict__ Wq,
                              const float* __restrict__ Wk,
                              const float* __restrict__ Wv)
{
    const int z = blockIdx.z;
    const float* W = (z == 0) ? Wq : (z == 1) ? Wk : Wv;
    int idx = blockIdx.x * 256 + threadIdx.x;       // over 512*512
    int n = idx >> 9, k = idx & 511;
    float x = W[k * HIDDEN + n];
    __nv_bfloat16 h, l;
    bf16_split(x, h, l);
    size_t o = (size_t)z * HIDDEN * HIDDEN + (size_t)n * HIDDEN + k;
    g_wth[o] = h; g_wtl[o] = l;
}

// ============================================================
// Warp-MMA GEMM core (mma.sync m16n8k16 bf16 hi/lo split),
// 2-stage cp.async pipeline + ldmatrix fragment loads.
// C tile 128x128, 8 warps (2m x 4n), warp tile 64x32, KC=32.
// Smem: 2 stages x 4 tiles x [128][40] bf16 = 81920 B (dynamic).
// ============================================================
#define KC          32
#define SPITCH      40
#define TILE_ELEMS  (128 * SPITCH)          // per tile, bf16 elems
#define STAGE_ELEMS (4 * TILE_ELEMS)
#define SMEM_BYTES  (2 * STAGE_ELEMS * 2)   // 81920

extern __shared__ __nv_bfloat16 dsm[];

__device__ __forceinline__ uint32_t smem_u32(const void* p) {
    uint32_t a;
    asm("{ .reg .u64 t; cvta.to.shared.u64 t, %1; cvt.u32.u64 %0, t; }" : "=r"(a) : "l"(p));
    return a;
}
__device__ __forceinline__ void cp16(uint32_t dst, const void* src) {
    asm volatile("cp.async.cg.shared.global [%0], [%1], 16;" :: "r"(dst), "l"(src));
}
__device__ __forceinline__ void cp_commit() {
    asm volatile("cp.async.commit_group;" ::: "memory");
}
template <int N>
__device__ __forceinline__ void cp_wait() {
    asm volatile("cp.async.wait_group %0;" :: "n"(N) : "memory");
}

__device__ __forceinline__ void mma16816(float c[4], const uint32_t a[4], const uint32_t b[2]) {
    asm volatile(
        "mma.sync.aligned.m16n8k16.row.col.f32.bf16.bf16.f32 "
        "{%0,%1,%2,%3}, {%4,%5,%6,%7}, {%8,%9}, {%0,%1,%2,%3};"
        : "+f"(c[0]), "+f"(c[1]), "+f"(c[2]), "+f"(c[3])
        : "r"(a[0]), "r"(a[1]), "r"(a[2]), "r"(a[3]), "r"(b[0]), "r"(b[1]));
}

__device__ __forceinline__ void ldsm4(uint32_t r[4], uint32_t addr) {
    asm volatile("ldmatrix.sync.aligned.m8n8.x4.shared.b16 {%0,%1,%2,%3}, [%4];"
                 : "=r"(r[0]), "=r"(r[1]), "=r"(r[2]), "=r"(r[3]) : "r"(addr));
}

// async copy of one 128x32 bf16 tile into padded smem tile
__device__ __forceinline__ void copy_tile_async(const __nv_bfloat16* __restrict__ src,
                                                size_t ld, uint32_t dst, int t)
{
    #pragma unroll
    for (int i = 0; i < 2; i++) {
        int idx = t + i * 256;
        int r = idx >> 2, c = idx & 3;
        cp16(dst + (uint32_t)(r * SPITCH + c * 8) * 2,
             src + (size_t)r * ld + c * 8);
    }
}

template <class Epi>
__device__ __forceinline__ void gemm_mma_body(
    const __nv_bfloat16* __restrict__ Ah, const __nv_bfloat16* __restrict__ Al, size_t lda,
    const __nv_bfloat16* __restrict__ Bh, const __nv_bfloat16* __restrict__ Bl, size_t ldb,
    int K, Epi epi)
{
    const int t    = threadIdx.x;
    const int lane = t & 31;
    const int wid  = t >> 5;
    const int wm   = (wid & 1) * 64;      // warp m-offset
    const int wn   = (wid >> 1) * 32;     // warp n-offset
    const int g    = lane >> 2;
    const int tg   = lane & 3;

    // ldmatrix per-lane source rows:
    // A (x4 over m16 x k16): quad 0:(m,k) 1:(m+8,k) 2:(m,k+8) 3:(m+8,k+8)
    // B (x4 over n16 x k16): quad 0:(n,k) 1:(n,k+8) 2:(n+8,k) 3:(n+8,k+8)
    const int lr = lane & 7, q = lane >> 3;
    const uint32_t a_off = (uint32_t)(((lr + (q & 1) * 8) * SPITCH) + (q & 2) * 4) * 2;
    const uint32_t b_off = (uint32_t)(((lr + (q & 2) * 4) * SPITCH) + (q & 1) * 8) * 2;

    const uint32_t sbase = smem_u32(dsm);
    const int kTiles = K / KC;

    float acc[4][4][4] = {};

    // prologue: prefetch stage 0
    {
        uint32_t st = sbase;
        copy_tile_async(Ah, lda, st,                       t);
        copy_tile_async(Al, lda, st + TILE_ELEMS * 2,      t);
        copy_tile_async(Bh, ldb, st + 2 * TILE_ELEMS * 2,  t);
        copy_tile_async(Bl, ldb, st + 3 * TILE_ELEMS * 2,  t);
        cp_commit();
    }

    int s = 0;
    for (int kb = 0; kb < kTiles; kb++) {
        if (kb + 1 < kTiles) {
            const size_t ko = (size_t)(kb + 1) * KC;
            uint32_t st = sbase + (uint32_t)((s ^ 1) * STAGE_ELEMS) * 2;
            copy_tile_async(Ah + ko, lda, st,                      t);
            copy_tile_async(Al + ko, lda, st + TILE_ELEMS * 2,     t);
            copy_tile_async(Bh + ko, ldb, st + 2 * TILE_ELEMS * 2, t);
            copy_tile_async(Bl + ko, ldb, st + 3 * TILE_ELEMS * 2, t);
            cp_commit();
            cp_wait<1>();
        } else {
            cp_wait<0>();
        }
        __syncthreads();

        const uint32_t stb = sbase + (uint32_t)(s * STAGE_ELEMS) * 2;
        const uint32_t aH = stb;
        const uint32_t aL = stb + TILE_ELEMS * 2;
        const uint32_t bH = stb + 2 * TILE_ELEMS * 2;
        const uint32_t bL = stb + 3 * TILE_ELEMS * 2;

        #pragma unroll
        for (int kk = 0; kk < KC; kk += 16) {
            uint32_t ah[4][4], al[4][4], bh[4][2], bl[4][2];
            #pragma unroll
            for (int mi = 0; mi < 4; mi++) {
                uint32_t row_off = (uint32_t)((wm + mi * 16) * SPITCH + kk) * 2;
                ldsm4(ah[mi], aH + a_off + row_off);
                ldsm4(al[mi], aL + a_off + row_off);
            }
            #pragma unroll
            for (int np = 0; np < 2; np++) {    // each x4 covers two n-groups
                uint32_t row_off = (uint32_t)((wn + np * 16) * SPITCH + kk) * 2;
                uint32_t rh[4], rl[4];
                ldsm4(rh, bH + b_off + row_off);
                ldsm4(rl, bL + b_off + row_off);
                bh[np * 2][0] = rh[0]; bh[np * 2][1] = rh[1];
                bh[np * 2 + 1][0] = rh[2]; bh[np * 2 + 1][1] = rh[3];
                bl[np * 2][0] = rl[0]; bl[np * 2][1] = rl[1];
                bl[np * 2 + 1][0] = rl[2]; bl[np * 2 + 1][1] = rl[3];
            }
            #pragma unroll
            for (int mi = 0; mi < 4; mi++)
                #pragma unroll
                for (int ni = 0; ni < 4; ni++) {
                    mma16816(acc[mi][ni], ah[mi], bh[ni]);
                    mma16816(acc[mi][ni], al[mi], bh[ni]);
                    mma16816(acc[mi][ni], ah[mi], bl[ni]);
                }
        }
        __syncthreads();
        s ^= 1;
    }

    #pragma unroll
    for (int mi = 0; mi < 4; mi++)
        #pragma unroll
        for (int ni = 0; ni < 4; ni++) {
            int r0 = wm + mi * 16 + g;
            int c0 = wn + ni * 8 + tg * 2;
            epi(r0,     c0,     acc[mi][ni][0]);
            epi(r0,     c0 + 1, acc[mi][ni][1]);
            epi(r0 + 8, c0,     acc[mi][ni][2]);
            epi(r0 + 8, c0 + 1, acc[mi][ni][3]);
        }
}

// ============================================================
// Kernel 2: q/k/v = act @ W + b  (warp MMA), epi splits hi/lo (V transposed)
// ============================================================
__global__ void __launch_bounds__(256) qkv_mma_kernel(const float* __restrict__ bq,
                                                      const float* __restrict__ bk,
                                                      const float* __restrict__ bv)
{
    const int z = blockIdx.z;
    const int tile_n = blockIdx.x * 128;
    const int tile_m = blockIdx.y * 128;
    const float* bias = (z == 0) ? bq : (z == 1) ? bk : bv;

    const __nv_bfloat16* Ah = g_acth + (size_t)tile_m * HIDDEN;
    const __nv_bfloat16* Al = g_actl + (size_t)tile_m * HIDDEN;
    const __nv_bfloat16* Bh = g_wth + (size_t)z * HIDDEN * HIDDEN + (size_t)tile_n * HIDDEN;
    const __nv_bfloat16* Bl = g_wtl + (size_t)z * HIDDEN * HIDDEN + (size_t)tile_n * HIDDEN;

    gemm_mma_body(Ah, Al, HIDDEN, Bh, Bl, HIDDEN, HIDDEN,
        [&](int r, int c, float v) {
            int row = tile_m + r, col = tile_n + c;
            float x = v + bias[col];
            __nv_bfloat16 h, l;
            bf16_split(x, h, l);
            if (z == 2) {
                int b = row >> 11, s = row & (SEQ - 1);
                size_t o = ((size_t)b * HIDDEN + col) * SEQ + s;
                g_vth[o] = h; g_vtl[o] = l;
            } else {
                size_t o = (size_t)row * HIDDEN + col;
                if (z == 0) { g_qh[o] = h; g_ql[o] = l; }
                else        { g_kh[o] = h; g_kl[o] = l; }
            }
        });
}

// ============================================================
// Kernel 3: scores = (Q @ K^T) / sqrt(512)  (warp MMA)
// ============================================================
__global__ void __launch_bounds__(256) scores_mma_kernel()
{
    const int z = blockIdx.z;
    const int tile_n = blockIdx.x * 128;
    const int tile_m = blockIdx.y * 128;
    const __nv_bfloat16* Ah = g_qh + ((size_t)z * SEQ + tile_m) * HIDDEN;
    const __nv_bfloat16* Al = g_ql + ((size_t)z * SEQ + tile_m) * HIDDEN;
    const __nv_bfloat16* Bh = g_kh + ((size_t)z * SEQ + tile_n) * HIDDEN;
    const __nv_bfloat16* Bl = g_kl + ((size_t)z * SEQ + tile_n) * HIDDEN;
    float* C = g_scores + (size_t)z * SEQ * SEQ + (size_t)tile_m * SEQ + tile_n;
    const float scale = 0.04419417382415922f;   // 1/sqrt(512)

    gemm_mma_body(Ah, Al, HIDDEN, Bh, Bl, HIDDEN, HIDDEN,
        [&](int r, int c, float v) {
            C[(size_t)r * SEQ + c] = v * scale;
        });
}

// ============================================================
// Kernel 4: row softmax; writes attn bf16 hi/lo
// ============================================================
__global__ void softmax_kernel()
{
    const int row = blockIdx.x;
    const float* p = g_scores + (size_t)row * SEQ;
    __nv_bfloat16* oh = g_ah + (size_t)row * SEQ;
    __nv_bfloat16* ol = g_al + (size_t)row * SEQ;
    const int t = threadIdx.x;
    __shared__ float red[16];

    float v[8];
    float lmax = -1e30f;
    #pragma unroll
    for (int i = 0; i < 8; i++) {
        v[i] = p[t + i * 256];
        lmax = fmaxf(lmax, v[i]);
    }
    #pragma unroll
    for (int o = 16; o; o >>= 1)
        lmax = fmaxf(lmax, __shfl_xor_sync(0xffffffffu, lmax, o));
    if ((t & 31) == 0) red[t >> 5] = lmax;
    __syncthreads();
    float rmax = red[0];
    #pragma unroll
    for (int i = 1; i < 8; i++) rmax = fmaxf(rmax, red[i]);

    float lsum = 0.0f;
    #pragma unroll
    for (int i = 0; i < 8; i++) {
        v[i] = __expf(v[i] - rmax);
        lsum += v[i];
    }
    #pragma unroll
    for (int o = 16; o; o >>= 1)
        lsum += __shfl_xor_sync(0xffffffffu, lsum, o);
    if ((t & 31) == 0) red[8 + (t >> 5)] = lsum;
    __syncthreads();
    float total = 0.0f;
    #pragma unroll
    for (int i = 0; i < 8; i++) total += red[8 + i];

    float inv = 1.0f / total;
    #pragma unroll
    for (int i = 0; i < 8; i++) {
        float pr = v[i] * inv;
        __nv_bfloat16 h, l;
        bf16_split(pr, h, l);
        oh[t + i * 256] = h;
        ol[t + i * 256] = l;
    }
}

// ============================================================
// Kernel 5: out = attn @ V  (warp MMA, B = V^T K-major over tokens)
// ============================================================
__global__ void __launch_bounds__(256) out_mma_kernel(float* __restrict__ out)
{
    const int z = blockIdx.z;
    const int tile_n = blockIdx.x * 128;   // head dim
    const int tile_m = blockIdx.y * 128;   // query pos
    const __nv_bfloat16* Ah = g_ah + (size_t)z * SEQ * SEQ + (size_t)tile_m * SEQ;
    const __nv_bfloat16* Al = g_al + (size_t)z * SEQ * SEQ + (size_t)tile_m * SEQ;
    const __nv_bfloat16* Bh = g_vth + ((size_t)z * HIDDEN + tile_n) * SEQ;
    const __nv_bfloat16* Bl = g_vtl + ((size_t)z * HIDDEN + tile_n) * SEQ;
    float* C = out + ((size_t)z * SEQ + tile_m) * HIDDEN + tile_n;

    gemm_mma_body(Ah, Al, SEQ, Bh, Bl, SEQ, SEQ,
        [&](int r, int c, float v) {
            C[(size_t)r * HIDDEN + c] = v;
        });
}

// ============================================================
// launch
// ============================================================
extern "C" void kernel_launch(void* const* d_in, const int* in_sizes, int n_in,
                              void* d_out, int out_size)
{
    const int*   tok = (const int*)  d_in[0];
    const float* emb = (const float*)d_in[1];
    const float* W1  = (const float*)d_in[2];
    const float* b1  = (const float*)d_in[3];
    const float* Wq  = (const float*)d_in[4];
    const float* bq  = (const float*)d_in[5];
    const float* Wk  = (const float*)d_in[6];
    const float* bk  = (const float*)d_in[7];
    const float* Wv  = (const float*)d_in[8];
    const float* bv  = (const float*)d_in[9];
    float* out = (float*)d_out;

    static int smem_set = 0;
    if (!smem_set) {
        (void)cudaFuncSetAttribute(qkv_mma_kernel,
                                   cudaFuncAttributeMaxDynamicSharedMemorySize, SMEM_BYTES);
        (void)cudaFuncSetAttribute(scores_mma_kernel,
                                   cudaFuncAttributeMaxDynamicSharedMemorySize, SMEM_BYTES);
        (void)cudaFuncSetAttribute(out_mma_kernel,
                                   cudaFuncAttributeMaxDynamicSharedMemorySize, SMEM_BYTES);
        smem_set = 1;
    }

    dim3 blk(256);
    embed_mlp_kernel<<<dim3(HIDDEN / 64, ROWS / 64), blk>>>(tok, emb, W1, b1);
    wsplit_kernel<<<dim3(HIDDEN * HIDDEN / 256, 1, 3), blk>>>(Wq, Wk, Wv);
    qkv_mma_kernel<<<dim3(HIDDEN / 128, ROWS / 128, 3), blk, SMEM_BYTES>>>(bq, bk, bv);
    scores_mma_kernel<<<dim3(SEQ / 128, SEQ / 128, BATCH), blk, SMEM_BYTES>>>();
    softmax_kernel<<<dim3(ROWS), blk>>>();
    out_mma_kernel<<<dim3(HIDDEN / 128, SEQ / 128, BATCH), blk, SMEM_BYTES>>>(out);
}

// round 13
// speedup vs baseline: 1.0466x; 1.0466x over previous
#include <cuda_runtime.h>
#include <cuda_bf16.h>
#include <math.h>
#include <stdint.h>

#define BATCH  4
#define SEQ    2048
#define EMBED  256
#define HIDDEN 512
#define ROWS   (BATCH * SEQ)   // 8192

// -------- scratch (allocation-free: __device__ globals) --------
__device__ __align__(16) __nv_bfloat16 g_eh[ROWS * EMBED];               // 4 MB gathered emb hi
__device__ __align__(16) __nv_bfloat16 g_el[ROWS * EMBED];
__device__ __align__(16) __nv_bfloat16 g_w1h[HIDDEN * EMBED];            // W1^T hi [n][k]
__device__ __align__(16) __nv_bfloat16 g_w1l[HIDDEN * EMBED];
__device__ __align__(16) __nv_bfloat16 g_acth[ROWS * HIDDEN];            // 8 MB
__device__ __align__(16) __nv_bfloat16 g_actl[ROWS * HIDDEN];
__device__ __align__(16) __nv_bfloat16 g_wth[3 * HIDDEN * HIDDEN];       // W^T hi  [z][n][k]
__device__ __align__(16) __nv_bfloat16 g_wtl[3 * HIDDEN * HIDDEN];
__device__ __align__(16) __nv_bfloat16 g_qh[ROWS * HIDDEN];
__device__ __align__(16) __nv_bfloat16 g_ql[ROWS * HIDDEN];
__device__ __align__(16) __nv_bfloat16 g_kh[ROWS * HIDDEN];
__device__ __align__(16) __nv_bfloat16 g_kl[ROWS * HIDDEN];
__device__ __align__(16) __nv_bfloat16 g_vth[BATCH * HIDDEN * SEQ];      // V^T [b][h][s]
__device__ __align__(16) __nv_bfloat16 g_vtl[BATCH * HIDDEN * SEQ];
__device__ float g_scores[(size_t)BATCH * SEQ * SEQ];                    // 64 MB
__device__ __align__(16) __nv_bfloat16 g_ah[(size_t)BATCH * SEQ * SEQ];  // attn hi
__device__ __align__(16) __nv_bfloat16 g_al[(size_t)BATCH * SEQ * SEQ];  // attn lo

__device__ __forceinline__ void bf16_split(float x, __nv_bfloat16& h, __nv_bfloat16& l) {
    h = __float2bfloat16_rn(x);
    l = __float2bfloat16_rn(x - __bfloat162float(h));
}

// ============================================================
// Prep kernels: gather/split emb rows; transpose+split weights
// ============================================================
__global__ void esplit_kernel(const int* __restrict__ tok,
                              const float* __restrict__ emb)
{
    int idx = blockIdx.x * 256 + threadIdx.x;       // over ROWS*EMBED
    int row = idx >> 8, col = idx & 255;
    int token = tok[row];
    float x = emb[(size_t)token * EMBED + col];
    __nv_bfloat16 h, l;
    bf16_split(x, h, l);
    g_eh[idx] = h; g_el[idx] = l;
}

__global__ void w1split_kernel(const float* __restrict__ W1)
{
    int idx = blockIdx.x * 256 + threadIdx.x;       // over HIDDEN*EMBED
    int n = idx >> 8, k = idx & 255;
    float x = W1[k * HIDDEN + n];
    __nv_bfloat16 h, l;
    bf16_split(x, h, l);
    g_w1h[idx] = h; g_w1l[idx] = l;
}

__global__ void wsplit_kernel(const float* __restrict__ Wq,
                              const float* __restrict__ Wk,
                              const float* __restrict__ Wv)
{
    const int z = blockIdx.z;
    const float* W = (z == 0) ? Wq : (z == 1) ? Wk : Wv;
    int idx = blockIdx.x * 256 + threadIdx.x;       // over 512*512
    int n = idx >> 9, k = idx & 511;
    float x = W[k * HIDDEN + n];
    __nv_bfloat16 h, l;
    bf16_split(x, h, l);
    size_t o = (size_t)z * HIDDEN * HIDDEN + (size_t)n * HIDDEN + k;
    g_wth[o] = h; g_wtl[o] = l;
}

// ============================================================
// Warp-MMA GEMM core (mma.sync m16n8k16 bf16 hi/lo split),
// 2-stage cp.async pipeline + ldmatrix + PASS-MAJOR MMA order.
// C tile 128x128, 8 warps (2m x 4n), warp tile 64x32, KC=32.
// ============================================================
#define KC          32
#define SPITCH      40
#define TILE_ELEMS  (128 * SPITCH)          // per tile, bf16 elems
#define STAGE_ELEMS (4 * TILE_ELEMS)
#define SMEM_BYTES  (2 * STAGE_ELEMS * 2)   // 81920

extern __shared__ __nv_bfloat16 dsm[];

__device__ __forceinline__ uint32_t smem_u32(const void* p) {
    uint32_t a;
    asm("{ .reg .u64 t; cvta.to.shared.u64 t, %1; cvt.u32.u64 %0, t; }" : "=r"(a) : "l"(p));
    return a;
}
__device__ __forceinline__ void cp16(uint32_t dst, const void* src) {
    asm volatile("cp.async.cg.shared.global [%0], [%1], 16;" :: "r"(dst), "l"(src));
}
__device__ __forceinline__ void cp_commit() {
    asm volatile("cp.async.commit_group;" ::: "memory");
}
template <int N>
__device__ __forceinline__ void cp_wait() {
    asm volatile("cp.async.wait_group %0;" :: "n"(N) : "memory");
}

__device__ __forceinline__ void mma16816(float c[4], const uint32_t a[4], const uint32_t b[2]) {
    asm volatile(
        "mma.sync.aligned.m16n8k16.row.col.f32.bf16.bf16.f32 "
        "{%0,%1,%2,%3}, {%4,%5,%6,%7}, {%8,%9}, {%0,%1,%2,%3};"
        : "+f"(c[0]), "+f"(c[1]), "+f"(c[2]), "+f"(c[3])
        : "r"(a[0]), "r"(a[1]), "r"(a[2]), "r"(a[3]), "r"(b[0]), "r"(b[1]));
}

__device__ __forceinline__ void ldsm4(uint32_t r[4], uint32_t addr) {
    asm volatile("ldmatrix.sync.aligned.m8n8.x4.shared.b16 {%0,%1,%2,%3}, [%4];"
                 : "=r"(r[0]), "=r"(r[1]), "=r"(r[2]), "=r"(r[3]) : "r"(addr));
}

// async copy of one 128x32 bf16 tile into padded smem tile
__device__ __forceinline__ void copy_tile_async(const __nv_bfloat16* __restrict__ src,
                                                size_t ld, uint32_t dst, int t)
{
    #pragma unroll
    for (int i = 0; i < 2; i++) {
        int idx = t + i * 256;
        int r = idx >> 2, c = idx & 3;
        cp16(dst + (uint32_t)(r * SPITCH + c * 8) * 2,
             src + (size_t)r * ld + c * 8);
    }
}

template <class Epi>
__device__ __forceinline__ void gemm_mma_body(
    const __nv_bfloat16* __restrict__ Ah, const __nv_bfloat16* __restrict__ Al, size_t lda,
    const __nv_bfloat16* __restrict__ Bh, const __nv_bfloat16* __restrict__ Bl, size_t ldb,
    int K, Epi epi)
{
    const int t    = threadIdx.x;
    const int lane = t & 31;
    const int wid  = t >> 5;
    const int wm   = (wid & 1) * 64;      // warp m-offset
    const int wn   = (wid >> 1) * 32;     // warp n-offset
    const int g    = lane >> 2;
    const int tg   = lane & 3;

    // ldmatrix per-lane source rows (validated R12: bit-identical to manual loads)
    const int lr = lane & 7, q = lane >> 3;
    const uint32_t a_off = (uint32_t)(((lr + (q & 1) * 8) * SPITCH) + (q & 2) * 4) * 2;
    const uint32_t b_off = (uint32_t)(((lr + (q & 2) * 4) * SPITCH) + (q & 1) * 8) * 2;

    const uint32_t sbase = smem_u32(dsm);
    const int kTiles = K / KC;

    float acc[4][4][4] = {};

    // prologue: prefetch stage 0
    {
        uint32_t st = sbase;
        copy_tile_async(Ah, lda, st,                       t);
        copy_tile_async(Al, lda, st + TILE_ELEMS * 2,      t);
        copy_tile_async(Bh, ldb, st + 2 * TILE_ELEMS * 2,  t);
        copy_tile_async(Bl, ldb, st + 3 * TILE_ELEMS * 2,  t);
        cp_commit();
    }

    int s = 0;
    for (int kb = 0; kb < kTiles; kb++) {
        if (kb + 1 < kTiles) {
            const size_t ko = (size_t)(kb + 1) * KC;
            uint32_t st = sbase + (uint32_t)((s ^ 1) * STAGE_ELEMS) * 2;
            copy_tile_async(Ah + ko, lda, st,                      t);
            copy_tile_async(Al + ko, lda, st + TILE_ELEMS * 2,     t);
            copy_tile_async(Bh + ko, ldb, st + 2 * TILE_ELEMS * 2, t);
            copy_tile_async(Bl + ko, ldb, st + 3 * TILE_ELEMS * 2, t);
            cp_commit();
            cp_wait<1>();
        } else {
            cp_wait<0>();
        }
        __syncthreads();

        const uint32_t stb = sbase + (uint32_t)(s * STAGE_ELEMS) * 2;
        const uint32_t aH = stb;
        const uint32_t aL = stb + TILE_ELEMS * 2;
        const uint32_t bH = stb + 2 * TILE_ELEMS * 2;
        const uint32_t bL = stb + 3 * TILE_ELEMS * 2;

        #pragma unroll
        for (int kk = 0; kk < KC; kk += 16) {
            uint32_t ah[4][4], al[4][4], bh[4][2], bl[4][2];
            #pragma unroll
            for (int mi = 0; mi < 4; mi++) {
                uint32_t row_off = (uint32_t)((wm + mi * 16) * SPITCH + kk) * 2;
                ldsm4(ah[mi], aH + a_off + row_off);
                ldsm4(al[mi], aL + a_off + row_off);
            }
            #pragma unroll
            for (int np = 0; np < 2; np++) {    // each x4 covers two n-groups
                uint32_t row_off = (uint32_t)((wn + np * 16) * SPITCH + kk) * 2;
                uint32_t rh[4], rl[4];
                ldsm4(rh, bH + b_off + row_off);
                ldsm4(rl, bL + b_off + row_off);
                bh[np * 2][0] = rh[0]; bh[np * 2][1] = rh[1];
                bh[np * 2 + 1][0] = rh[2]; bh[np * 2 + 1][1] = rh[3];
                bl[np * 2][0] = rl[0]; bl[np * 2][1] = rl[1];
                bl[np * 2 + 1][0] = rl[2]; bl[np * 2 + 1][1] = rl[3];
            }
            // PASS-MAJOR order: dependent MMAs into the same accumulator are
            // spaced 16 instructions apart (volatile asm preserves this order).
            // Per-accumulator sequence stays hh -> lh -> hl (numerics identical).
            #pragma unroll
            for (int mi = 0; mi < 4; mi++)
                #pragma unroll
                for (int ni = 0; ni < 4; ni++)
                    mma16816(acc[mi][ni], ah[mi], bh[ni]);
            #pragma unroll
            for (int mi = 0; mi < 4; mi++)
                #pragma unroll
                for (int ni = 0; ni < 4; ni++)
                    mma16816(acc[mi][ni], al[mi], bh[ni]);
            #pragma unroll
            for (int mi = 0; mi < 4; mi++)
                #pragma unroll
                for (int ni = 0; ni < 4; ni++)
                    mma16816(acc[mi][ni], ah[mi], bl[ni]);
        }
        __syncthreads();
        s ^= 1;
    }

    #pragma unroll
    for (int mi = 0; mi < 4; mi++)
        #pragma unroll
        for (int ni = 0; ni < 4; ni++) {
            int r0 = wm + mi * 16 + g;
            int c0 = wn + ni * 8 + tg * 2;
            epi(r0,     c0,     acc[mi][ni][0]);
            epi(r0,     c0 + 1, acc[mi][ni][1]);
            epi(r0 + 8, c0,     acc[mi][ni][2]);
            epi(r0 + 8, c0 + 1, acc[mi][ni][3]);
        }
}

// ============================================================
// Kernel 1: act = gelu( emb @ W1 + b1 )  (warp MMA over split emb)
// ============================================================
__global__ void __launch_bounds__(256) embed_mma_kernel(const float* __restrict__ b1)
{
    const int tile_n = blockIdx.x * 128;
    const int tile_m = blockIdx.y * 128;
    const __nv_bfloat16* Ah = g_eh + (size_t)tile_m * EMBED;
    const __nv_bfloat16* Al = g_el + (size_t)tile_m * EMBED;
    const __nv_bfloat16* Bh = g_w1h + (size_t)tile_n * EMBED;
    const __nv_bfloat16* Bl = g_w1l + (size_t)tile_n * EMBED;

    gemm_mma_body(Ah, Al, EMBED, Bh, Bl, EMBED, EMBED,
        [&](int r, int c, float v) {
            int row = tile_m + r, col = tile_n + c;
            float x = v + b1[col];
            float gl = 0.5f * x * (1.0f + erff(x * 0.7071067811865475f));
            __nv_bfloat16 h, l;
            bf16_split(gl, h, l);
            size_t o = (size_t)row * HIDDEN + col;
            g_acth[o] = h; g_actl[o] = l;
        });
}

// ============================================================
// Kernel 2: q/k/v = act @ W + b  (warp MMA), epi splits hi/lo (V transposed)
// ============================================================
__global__ void __launch_bounds__(256) qkv_mma_kernel(const float* __restrict__ bq,
                                                      const float* __restrict__ bk,
                                                      const float* __restrict__ bv)
{
    const int z = blockIdx.z;
    const int tile_n = blockIdx.x * 128;
    const int tile_m = blockIdx.y * 128;
    const float* bias = (z == 0) ? bq : (z == 1) ? bk : bv;

    const __nv_bfloat16* Ah = g_acth + (size_t)tile_m * HIDDEN;
    const __nv_bfloat16* Al = g_actl + (size_t)tile_m * HIDDEN;
    const __nv_bfloat16* Bh = g_wth + (size_t)z * HIDDEN * HIDDEN + (size_t)tile_n * HIDDEN;
    const __nv_bfloat16* Bl = g_wtl + (size_t)z * HIDDEN * HIDDEN + (size_t)tile_n * HIDDEN;

    gemm_mma_body(Ah, Al, HIDDEN, Bh, Bl, HIDDEN, HIDDEN,
        [&](int r, int c, float v) {
            int row = tile_m + r, col = tile_n + c;
            float x = v + bias[col];
            __nv_bfloat16 h, l;
            bf16_split(x, h, l);
            if (z == 2) {
                int b = row >> 11, s = row & (SEQ - 1);
                size_t o = ((size_t)b * HIDDEN + col) * SEQ + s;
                g_vth[o] = h; g_vtl[o] = l;
            } else {
                size_t o = (size_t)row * HIDDEN + col;
                if (z == 0) { g_qh[o] = h; g_ql[o] = l; }
                else        { g_kh[o] = h; g_kl[o] = l; }
            }
        });
}

// ============================================================
// Kernel 3: scores = (Q @ K^T) / sqrt(512)  (warp MMA)
// ============================================================
__global__ void __launch_bounds__(256) scores_mma_kernel()
{
    const int z = blockIdx.z;
    const int tile_n = blockIdx.x * 128;
    const int tile_m = blockIdx.y * 128;
    const __nv_bfloat16* Ah = g_qh + ((size_t)z * SEQ + tile_m) * HIDDEN;
    const __nv_bfloat16* Al = g_ql + ((size_t)z * SEQ + tile_m) * HIDDEN;
    const __nv_bfloat16* Bh = g_kh + ((size_t)z * SEQ + tile_n) * HIDDEN;
    const __nv_bfloat16* Bl = g_kl + ((size_t)z * SEQ + tile_n) * HIDDEN;
    float* C = g_scores + (size_t)z * SEQ * SEQ + (size_t)tile_m * SEQ + tile_n;
    const float scale = 0.04419417382415922f;   // 1/sqrt(512)

    gemm_mma_body(Ah, Al, HIDDEN, Bh, Bl, HIDDEN, HIDDEN,
        [&](int r, int c, float v) {
            C[(size_t)r * SEQ + c] = v * scale;
        });
}

// ============================================================
// Kernel 4: row softmax; writes attn bf16 hi/lo
// ============================================================
__global__ void softmax_kernel()
{
    const int row = blockIdx.x;
    const float* p = g_scores + (size_t)row * SEQ;
    __nv_bfloat16* oh = g_ah + (size_t)row * SEQ;
    __nv_bfloat16* ol = g_al + (size_t)row * SEQ;
    const int t = threadIdx.x;
    __shared__ float red[16];

    float v[8];
    float lmax = -1e30f;
    #pragma unroll
    for (int i = 0; i < 8; i++) {
        v[i] = p[t + i * 256];
        lmax = fmaxf(lmax, v[i]);
    }
    #pragma unroll
    for (int o = 16; o; o >>= 1)
        lmax = fmaxf(lmax, __shfl_xor_sync(0xffffffffu, lmax, o));
    if ((t & 31) == 0) red[t >> 5] = lmax;
    __syncthreads();
    float rmax = red[0];
    #pragma unroll
    for (int i = 1; i < 8; i++) rmax = fmaxf(rmax, red[i]);

    float lsum = 0.0f;
    #pragma unroll
    for (int i = 0; i < 8; i++) {
        v[i] = __expf(v[i] - rmax);
        lsum += v[i];
    }
    #pragma unroll
    for (int o = 16; o; o >>= 1)
        lsum += __shfl_xor_sync(0xffffffffu, lsum, o);
    if ((t & 31) == 0) red[8 + (t >> 5)] = lsum;
    __syncthreads();
    float total = 0.0f;
    #pragma unroll
    for (int i = 0; i < 8; i++) total += red[8 + i];

    float inv = 1.0f / total;
    #pragma unroll
    for (int i = 0; i < 8; i++) {
        float pr = v[i] * inv;
        __nv_bfloat16 h, l;
        bf16_split(pr, h, l);
        oh[t + i * 256] = h;
        ol[t + i * 256] = l;
    }
}

// ============================================================
// Kernel 5: out = attn @ V  (warp MMA, B = V^T K-major over tokens)
// ============================================================
__global__ void __launch_bounds__(256) out_mma_kernel(float* __restrict__ out)
{
    const int z = blockIdx.z;
    const int tile_n = blockIdx.x * 128;   // head dim
    const int tile_m = blockIdx.y * 128;   // query pos
    const __nv_bfloat16* Ah = g_ah + (size_t)z * SEQ * SEQ + (size_t)tile_m * SEQ;
    const __nv_bfloat16* Al = g_al + (size_t)z * SEQ * SEQ + (size_t)tile_m * SEQ;
    const __nv_bfloat16* Bh = g_vth + ((size_t)z * HIDDEN + tile_n) * SEQ;
    const __nv_bfloat16* Bl = g_vtl + ((size_t)z * HIDDEN + tile_n) * SEQ;
    float* C = out + ((size_t)z * SEQ + tile_m) * HIDDEN + tile_n;

    gemm_mma_body(Ah, Al, SEQ, Bh, Bl, SEQ, SEQ,
        [&](int r, int c, float v) {
            C[(size_t)r * HIDDEN + c] = v;
        });
}

// ============================================================
// launch
// ============================================================
extern "C" void kernel_launch(void* const* d_in, const int* in_sizes, int n_in,
                              void* d_out, int out_size)
{
    const int*   tok = (const int*)  d_in[0];
    const float* emb = (const float*)d_in[1];
    const float* W1  = (const float*)d_in[2];
    const float* b1  = (const float*)d_in[3];
    const float* Wq  = (const float*)d_in[4];
    const float* bq  = (const float*)d_in[5];
    const float* Wk  = (const float*)d_in[6];
    const float* bk  = (const float*)d_in[7];
    const float* Wv  = (const float*)d_in[8];
    const float* bv  = (const float*)d_in[9];
    float* out = (float*)d_out;

    static int smem_set = 0;
    if (!smem_set) {
        (void)cudaFuncSetAttribute(embed_mma_kernel,
                                   cudaFuncAttributeMaxDynamicSharedMemorySize, SMEM_BYTES);
        (void)cudaFuncSetAttribute(qkv_mma_kernel,
                                   cudaFuncAttributeMaxDynamicSharedMemorySize, SMEM_BYTES);
        (void)cudaFuncSetAttribute(scores_mma_kernel,
                                   cudaFuncAttributeMaxDynamicSharedMemorySize, SMEM_BYTES);
        (void)cudaFuncSetAttribute(out_mma_kernel,
                                   cudaFuncAttributeMaxDynamicSharedMemorySize, SMEM_BYTES);
        smem_set = 1;
    }

    dim3 blk(256);
    esplit_kernel<<<dim3(ROWS * EMBED / 256), blk>>>(tok, emb);
    w1split_kernel<<<dim3(HIDDEN * EMBED / 256), blk>>>(W1);
    wsplit_kernel<<<dim3(HIDDEN * HIDDEN / 256, 1, 3), blk>>>(Wq, Wk, Wv);
    embed_mma_kernel<<<dim3(HIDDEN / 128, ROWS / 128), blk, SMEM_BYTES>>>(b1);
    qkv_mma_kernel<<<dim3(HIDDEN / 128, ROWS / 128, 3), blk, SMEM_BYTES>>>(bq, bk, bv);
    scores_mma_kernel<<<dim3(SEQ / 128, SEQ / 128, BATCH), blk, SMEM_BYTES>>>();
    softmax_kernel<<<dim3(ROWS), blk>>>();
    out_mma_kernel<<<dim3(HIDDEN / 128, SEQ / 128, BATCH), blk, SMEM_BYTES>>>(out);
}

// round 14
// speedup vs baseline: 1.1141x; 1.0645x over previous
#include <cuda_runtime.h>
#include <cuda_bf16.h>
#include <math.h>
#include <stdint.h>

#define BATCH  4
#define SEQ    2048
#define EMBED  256
#define HIDDEN 512
#define ROWS   (BATCH * SEQ)   // 8192

// -------- scratch (allocation-free: __device__ globals) --------
__device__ __align__(16) __nv_bfloat16 g_eh[ROWS * EMBED];               // 4 MB gathered emb hi
__device__ __align__(16) __nv_bfloat16 g_el[ROWS * EMBED];
__device__ __align__(16) __nv_bfloat16 g_w1h[HIDDEN * EMBED];            // W1^T hi [n][k]
__device__ __align__(16) __nv_bfloat16 g_w1l[HIDDEN * EMBED];
__device__ __align__(16) __nv_bfloat16 g_acth[ROWS * HIDDEN];            // 8 MB
__device__ __align__(16) __nv_bfloat16 g_actl[ROWS * HIDDEN];
__device__ __align__(16) __nv_bfloat16 g_wth[3 * HIDDEN * HIDDEN];       // W^T hi  [z][n][k]
__device__ __align__(16) __nv_bfloat16 g_wtl[3 * HIDDEN * HIDDEN];
__device__ __align__(16) __nv_bfloat16 g_qh[ROWS * HIDDEN];
__device__ __align__(16) __nv_bfloat16 g_ql[ROWS * HIDDEN];
__device__ __align__(16) __nv_bfloat16 g_kh[ROWS * HIDDEN];
__device__ __align__(16) __nv_bfloat16 g_kl[ROWS * HIDDEN];
__device__ __align__(16) __nv_bfloat16 g_vth[BATCH * HIDDEN * SEQ];      // V^T [b][h][s]
__device__ __align__(16) __nv_bfloat16 g_vtl[BATCH * HIDDEN * SEQ];
__device__ float g_scores[(size_t)BATCH * SEQ * SEQ];                    // 64 MB
__device__ __align__(16) __nv_bfloat16 g_ah[(size_t)BATCH * SEQ * SEQ];  // attn hi
__device__ __align__(16) __nv_bfloat16 g_al[(size_t)BATCH * SEQ * SEQ];  // attn lo

__device__ __forceinline__ void bf16_split(float x, __nv_bfloat16& h, __nv_bfloat16& l) {
    h = __float2bfloat16_rn(x);
    l = __float2bfloat16_rn(x - __bfloat162float(h));
}

// ============================================================
// Prep kernels: gather/split emb rows; transpose+split weights
// ============================================================
__global__ void esplit_kernel(const int* __restrict__ tok,
                              const float* __restrict__ emb)
{
    int idx = blockIdx.x * 256 + threadIdx.x;       // over ROWS*EMBED
    int row = idx >> 8, col = idx & 255;
    int token = tok[row];
    float x = emb[(size_t)token * EMBED + col];
    __nv_bfloat16 h, l;
    bf16_split(x, h, l);
    g_eh[idx] = h; g_el[idx] = l;
}

__global__ void w1split_kernel(const float* __restrict__ W1)
{
    int idx = blockIdx.x * 256 + threadIdx.x;       // over HIDDEN*EMBED
    int n = idx >> 8, k = idx & 255;
    float x = W1[k * HIDDEN + n];
    __nv_bfloat16 h, l;
    bf16_split(x, h, l);
    g_w1h[idx] = h; g_w1l[idx] = l;
}

__global__ void wsplit_kernel(const float* __restrict__ Wq,
                              const float* __restrict__ Wk,
                              const float* __restrict__ Wv)
{
    const int z = blockIdx.z;
    const float* W = (z == 0) ? Wq : (z == 1) ? Wk : Wv;
    int idx = blockIdx.x * 256 + threadIdx.x;       // over 512*512
    int n = idx >> 9, k = idx & 511;
    float x = W[k * HIDDEN + n];
    __nv_bfloat16 h, l;
    bf16_split(x, h, l);
    size_t o = (size_t)z * HIDDEN * HIDDEN + (size_t)n * HIDDEN + k;
    g_wth[o] = h; g_wtl[o] = l;
}

// ============================================================
// Warp-MMA GEMM core (mma.sync m16n8k16 bf16 hi/lo split),
// 2-stage cp.async pipeline + LDSM/MMA interleave.
// C tile 128x128, 8 warps (2m x 4n), warp tile 64x32, KC=32.
// ============================================================
#define KC          32
#define SPITCH      40
#define TILE_ELEMS  (128 * SPITCH)          // per tile, bf16 elems
#define STAGE_ELEMS (4 * TILE_ELEMS)
#define SMEM_BYTES  (2 * STAGE_ELEMS * 2)   // 81920

extern __shared__ __nv_bfloat16 dsm[];

__device__ __forceinline__ uint32_t smem_u32(const void* p) {
    uint32_t a;
    asm("{ .reg .u64 t; cvta.to.shared.u64 t, %1; cvt.u32.u64 %0, t; }" : "=r"(a) : "l"(p));
    return a;
}
__device__ __forceinline__ void cp16(uint32_t dst, const void* src) {
    asm volatile("cp.async.cg.shared.global [%0], [%1], 16;" :: "r"(dst), "l"(src));
}
__device__ __forceinline__ void cp_commit() {
    asm volatile("cp.async.commit_group;" ::: "memory");
}
template <int N>
__device__ __forceinline__ void cp_wait() {
    asm volatile("cp.async.wait_group %0;" :: "n"(N) : "memory");
}

__device__ __forceinline__ void mma16816(float c[4], const uint32_t a[4], const uint32_t b[2]) {
    asm volatile(
        "mma.sync.aligned.m16n8k16.row.col.f32.bf16.bf16.f32 "
        "{%0,%1,%2,%3}, {%4,%5,%6,%7}, {%8,%9}, {%0,%1,%2,%3};"
        : "+f"(c[0]), "+f"(c[1]), "+f"(c[2]), "+f"(c[3])
        : "r"(a[0]), "r"(a[1]), "r"(a[2]), "r"(a[3]), "r"(b[0]), "r"(b[1]));
}

__device__ __forceinline__ void ldsm4(uint32_t r[4], uint32_t addr) {
    asm volatile("ldmatrix.sync.aligned.m8n8.x4.shared.b16 {%0,%1,%2,%3}, [%4];"
                 : "=r"(r[0]), "=r"(r[1]), "=r"(r[2]), "=r"(r[3]) : "r"(addr));
}

// async copy of one 128x32 bf16 tile into padded smem tile
__device__ __forceinline__ void copy_tile_async(const __nv_bfloat16* __restrict__ src,
                                                size_t ld, uint32_t dst, int t)
{
    #pragma unroll
    for (int i = 0; i < 2; i++) {
        int idx = t + i * 256;
        int r = idx >> 2, c = idx & 3;
        cp16(dst + (uint32_t)(r * SPITCH + c * 8) * 2,
             src + (size_t)r * ld + c * 8);
    }
}

template <class Epi>
__device__ __forceinline__ void gemm_mma_body(
    const __nv_bfloat16* __restrict__ Ah, const __nv_bfloat16* __restrict__ Al, size_t lda,
    const __nv_bfloat16* __restrict__ Bh, const __nv_bfloat16* __restrict__ Bl, size_t ldb,
    int K, Epi epi)
{
    const int t    = threadIdx.x;
    const int lane = t & 31;
    const int wid  = t >> 5;
    const int wm   = (wid & 1) * 64;      // warp m-offset
    const int wn   = (wid >> 1) * 32;     // warp n-offset
    const int g    = lane >> 2;
    const int tg   = lane & 3;

    // ldmatrix per-lane source rows (validated R12: bit-identical to manual loads)
    const int lr = lane & 7, q = lane >> 3;
    const uint32_t a_off = (uint32_t)(((lr + (q & 1) * 8) * SPITCH) + (q & 2) * 4) * 2;
    const uint32_t b_off = (uint32_t)(((lr + (q & 2) * 4) * SPITCH) + (q & 1) * 8) * 2;

    const uint32_t sbase = smem_u32(dsm);
    const int kTiles = K / KC;

    float acc[4][4][4] = {};

    // prologue: prefetch stage 0
    {
        uint32_t st = sbase;
        copy_tile_async(Ah, lda, st,                       t);
        copy_tile_async(Al, lda, st + TILE_ELEMS * 2,      t);
        copy_tile_async(Bh, ldb, st + 2 * TILE_ELEMS * 2,  t);
        copy_tile_async(Bl, ldb, st + 3 * TILE_ELEMS * 2,  t);
        cp_commit();
    }

    int s = 0;
    for (int kb = 0; kb < kTiles; kb++) {
        if (kb + 1 < kTiles) {
            const size_t ko = (size_t)(kb + 1) * KC;
            uint32_t st = sbase + (uint32_t)((s ^ 1) * STAGE_ELEMS) * 2;
            copy_tile_async(Ah + ko, lda, st,                      t);
            copy_tile_async(Al + ko, lda, st + TILE_ELEMS * 2,     t);
            copy_tile_async(Bh + ko, ldb, st + 2 * TILE_ELEMS * 2, t);
            copy_tile_async(Bl + ko, ldb, st + 3 * TILE_ELEMS * 2, t);
            cp_commit();
            cp_wait<1>();
        } else {
            cp_wait<0>();
        }
        __syncthreads();

        const uint32_t stb = sbase + (uint32_t)(s * STAGE_ELEMS) * 2;
        const uint32_t aH = stb;
        const uint32_t aL = stb + TILE_ELEMS * 2;
        const uint32_t bH = stb + 2 * TILE_ELEMS * 2;
        const uint32_t bL = stb + 3 * TILE_ELEMS * 2;

        #pragma unroll
        for (int kk = 0; kk < KC; kk += 16) {
            uint32_t ah[4][4], al[4][4], bh[4][2], bl[4][2];
            // --- load only hi fragments first (6 LDSM head) ---
            #pragma unroll
            for (int mi = 0; mi < 4; mi++) {
                uint32_t row_off = (uint32_t)((wm + mi * 16) * SPITCH + kk) * 2;
                ldsm4(ah[mi], aH + a_off + row_off);
            }
            #pragma unroll
            for (int np = 0; np < 2; np++) {
                uint32_t row_off = (uint32_t)((wn + np * 16) * SPITCH + kk) * 2;
                uint32_t rh[4];
                ldsm4(rh, bH + b_off + row_off);
                bh[np * 2][0] = rh[0]; bh[np * 2][1] = rh[1];
                bh[np * 2 + 1][0] = rh[2]; bh[np * 2 + 1][1] = rh[3];
            }
            // --- pass hh, first half (mi 0..1) ---
            #pragma unroll
            for (int mi = 0; mi < 2; mi++)
                #pragma unroll
                for (int ni = 0; ni < 4; ni++)
                    mma16816(acc[mi][ni], ah[mi], bh[ni]);
            // --- load al under MMA cover ---
            #pragma unroll
            for (int mi = 0; mi < 4; mi++) {
                uint32_t row_off = (uint32_t)((wm + mi * 16) * SPITCH + kk) * 2;
                ldsm4(al[mi], aL + a_off + row_off);
            }
            // --- pass hh, second half (mi 2..3) ---
            #pragma unroll
            for (int mi = 2; mi < 4; mi++)
                #pragma unroll
                for (int ni = 0; ni < 4; ni++)
                    mma16816(acc[mi][ni], ah[mi], bh[ni]);
            // --- load bl under MMA cover ---
            #pragma unroll
            for (int np = 0; np < 2; np++) {
                uint32_t row_off = (uint32_t)((wn + np * 16) * SPITCH + kk) * 2;
                uint32_t rl[4];
                ldsm4(rl, bL + b_off + row_off);
                bl[np * 2][0] = rl[0]; bl[np * 2][1] = rl[1];
                bl[np * 2 + 1][0] = rl[2]; bl[np * 2 + 1][1] = rl[3];
            }
            // --- pass lh ---
            #pragma unroll
            for (int mi = 0; mi < 4; mi++)
                #pragma unroll
                for (int ni = 0; ni < 4; ni++)
                    mma16816(acc[mi][ni], al[mi], bh[ni]);
            // --- pass hl ---
            #pragma unroll
            for (int mi = 0; mi < 4; mi++)
                #pragma unroll
                for (int ni = 0; ni < 4; ni++)
                    mma16816(acc[mi][ni], ah[mi], bl[ni]);
        }
        __syncthreads();
        s ^= 1;
    }

    #pragma unroll
    for (int mi = 0; mi < 4; mi++)
        #pragma unroll
        for (int ni = 0; ni < 4; ni++) {
            int r0 = wm + mi * 16 + g;
            int c0 = wn + ni * 8 + tg * 2;
            epi(r0,     c0,     acc[mi][ni][0]);
            epi(r0,     c0 + 1, acc[mi][ni][1]);
            epi(r0 + 8, c0,     acc[mi][ni][2]);
            epi(r0 + 8, c0 + 1, acc[mi][ni][3]);
        }
}

// ============================================================
// Kernel 1: act = gelu( emb @ W1 + b1 )  (warp MMA over split emb)
// ============================================================
__global__ void __launch_bounds__(256, 2) embed_mma_kernel(const float* __restrict__ b1)
{
    const int tile_n = blockIdx.x * 128;
    const int tile_m = blockIdx.y * 128;
    const __nv_bfloat16* Ah = g_eh + (size_t)tile_m * EMBED;
    const __nv_bfloat16* Al = g_el + (size_t)tile_m * EMBED;
    const __nv_bfloat16* Bh = g_w1h + (size_t)tile_n * EMBED;
    const __nv_bfloat16* Bl = g_w1l + (size_t)tile_n * EMBED;

    gemm_mma_body(Ah, Al, EMBED, Bh, Bl, EMBED, EMBED,
        [&](int r, int c, float v) {
            int row = tile_m + r, col = tile_n + c;
            float x = v + b1[col];
            float gl = 0.5f * x * (1.0f + erff(x * 0.7071067811865475f));
            __nv_bfloat16 h, l;
            bf16_split(gl, h, l);
            size_t o = (size_t)row * HIDDEN + col;
            g_acth[o] = h; g_actl[o] = l;
        });
}

// ============================================================
// Kernel 2: q/k/v = act @ W + b  (warp MMA), epi splits hi/lo (V transposed)
// ============================================================
__global__ void __launch_bounds__(256, 2) qkv_mma_kernel(const float* __restrict__ bq,
                                                         const float* __restrict__ bk,
                                                         const float* __restrict__ bv)
{
    const int z = blockIdx.z;
    const int tile_n = blockIdx.x * 128;
    const int tile_m = blockIdx.y * 128;
    const float* bias = (z == 0) ? bq : (z == 1) ? bk : bv;

    const __nv_bfloat16* Ah = g_acth + (size_t)tile_m * HIDDEN;
    const __nv_bfloat16* Al = g_actl + (size_t)tile_m * HIDDEN;
    const __nv_bfloat16* Bh = g_wth + (size_t)z * HIDDEN * HIDDEN + (size_t)tile_n * HIDDEN;
    const __nv_bfloat16* Bl = g_wtl + (size_t)z * HIDDEN * HIDDEN + (size_t)tile_n * HIDDEN;

    gemm_mma_body(Ah, Al, HIDDEN, Bh, Bl, HIDDEN, HIDDEN,
        [&](int r, int c, float v) {
            int row = tile_m + r, col = tile_n + c;
            float x = v + bias[col];
            __nv_bfloat16 h, l;
            bf16_split(x, h, l);
            if (z == 2) {
                int b = row >> 11, s = row & (SEQ - 1);
                size_t o = ((size_t)b * HIDDEN + col) * SEQ + s;
                g_vth[o] = h; g_vtl[o] = l;
            } else {
                size_t o = (size_t)row * HIDDEN + col;
                if (z == 0) { g_qh[o] = h; g_ql[o] = l; }
                else        { g_kh[o] = h; g_kl[o] = l; }
            }
        });
}

// ============================================================
// Kernel 3: scores = (Q @ K^T) / sqrt(512)  (warp MMA)
// ============================================================
__global__ void __launch_bounds__(256, 2) scores_mma_kernel()
{
    const int z = blockIdx.z;
    const int tile_n = blockIdx.x * 128;
    const int tile_m = blockIdx.y * 128;
    const __nv_bfloat16* Ah = g_qh + ((size_t)z * SEQ + tile_m) * HIDDEN;
    const __nv_bfloat16* Al = g_ql + ((size_t)z * SEQ + tile_m) * HIDDEN;
    const __nv_bfloat16* Bh = g_kh + ((size_t)z * SEQ + tile_n) * HIDDEN;
    const __nv_bfloat16* Bl = g_kl + ((size_t)z * SEQ + tile_n) * HIDDEN;
    float* C = g_scores + (size_t)z * SEQ * SEQ + (size_t)tile_m * SEQ + tile_n;
    const float scale = 0.04419417382415922f;   // 1/sqrt(512)

    gemm_mma_body(Ah, Al, HIDDEN, Bh, Bl, HIDDEN, HIDDEN,
        [&](int r, int c, float v) {
            C[(size_t)r * SEQ + c] = v * scale;
        });
}

// ============================================================
// Kernel 4: row softmax; writes attn bf16 hi/lo
// ============================================================
__global__ void softmax_kernel()
{
    const int row = blockIdx.x;
    const float* p = g_scores + (size_t)row * SEQ;
    __nv_bfloat16* oh = g_ah + (size_t)row * SEQ;
    __nv_bfloat16* ol = g_al + (size_t)row * SEQ;
    const int t = threadIdx.x;
    __shared__ float red[16];

    float v[8];
    float lmax = -1e30f;
    #pragma unroll
    for (int i = 0; i < 8; i++) {
        v[i] = p[t + i * 256];
        lmax = fmaxf(lmax, v[i]);
    }
    #pragma unroll
    for (int o = 16; o; o >>= 1)
        lmax = fmaxf(lmax, __shfl_xor_sync(0xffffffffu, lmax, o));
    if ((t & 31) == 0) red[t >> 5] = lmax;
    __syncthreads();
    float rmax = red[0];
    #pragma unroll
    for (int i = 1; i < 8; i++) rmax = fmaxf(rmax, red[i]);

    float lsum = 0.0f;
    #pragma unroll
    for (int i = 0; i < 8; i++) {
        v[i] = __expf(v[i] - rmax);
        lsum += v[i];
    }
    #pragma unroll
    for (int o = 16; o; o >>= 1)
        lsum += __shfl_xor_sync(0xffffffffu, lsum, o);
    if ((t & 31) == 0) red[8 + (t >> 5)] = lsum;
    __syncthreads();
    float total = 0.0f;
    #pragma unroll
    for (int i = 0; i < 8; i++) total += red[8 + i];

    float inv = 1.0f / total;
    #pragma unroll
    for (int i = 0; i < 8; i++) {
        float pr = v[i] * inv;
        __nv_bfloat16 h, l;
        bf16_split(pr, h, l);
        oh[t + i * 256] = h;
        ol[t + i * 256] = l;
    }
}

// ============================================================
// Kernel 5: out = attn @ V  (warp MMA, B = V^T K-major over tokens)
// ============================================================
__global__ void __launch_bounds__(256, 2) out_mma_kernel(float* __restrict__ out)
{
    const int z = blockIdx.z;
    const int tile_n = blockIdx.x * 128;   // head dim
    const int tile_m = blockIdx.y * 128;   // query pos
    const __nv_bfloat16* Ah = g_ah + (size_t)z * SEQ * SEQ + (size_t)tile_m * SEQ;
    const __nv_bfloat16* Al = g_al + (size_t)z * SEQ * SEQ + (size_t)tile_m * SEQ;
    const __nv_bfloat16* Bh = g_vth + ((size_t)z * HIDDEN + tile_n) * SEQ;
    const __nv_bfloat16* Bl = g_vtl + ((size_t)z * HIDDEN + tile_n) * SEQ;
    float* C = out + ((size_t)z * SEQ + tile_m) * HIDDEN + tile_n;

    gemm_mma_body(Ah, Al, SEQ, Bh, Bl, SEQ, SEQ,
        [&](int r, int c, float v) {
            C[(size_t)r * HIDDEN + c] = v;
        });
}

// ============================================================
// launch
// ============================================================
extern "C" void kernel_launch(void* const* d_in, const int* in_sizes, int n_in,
                              void* d_out, int out_size)
{
    const int*   tok = (const int*)  d_in[0];
    const float* emb = (const float*)d_in[1];
    const float* W1  = (const float*)d_in[2];
    const float* b1  = (const float*)d_in[3];
    const float* Wq  = (const float*)d_in[4];
    const float* bq  = (const float*)d_in[5];
    const float* Wk  = (const float*)d_in[6];
    const float* bk  = (const float*)d_in[7];
    const float* Wv  = (const float*)d_in[8];
    const float* bv  = (const float*)d_in[9];
    float* out = (float*)d_out;

    static int smem_set = 0;
    if (!smem_set) {
        (void)cudaFuncSetAttribute(embed_mma_kernel,
                                   cudaFuncAttributeMaxDynamicSharedMemorySize, SMEM_BYTES);
        (void)cudaFuncSetAttribute(qkv_mma_kernel,
                                   cudaFuncAttributeMaxDynamicSharedMemorySize, SMEM_BYTES);
        (void)cudaFuncSetAttribute(scores_mma_kernel,
                                   cudaFuncAttributeMaxDynamicSharedMemorySize, SMEM_BYTES);
        (void)cudaFuncSetAttribute(out_mma_kernel,
                                   cudaFuncAttributeMaxDynamicSharedMemorySize, SMEM_BYTES);
        smem_set = 1;
    }

    dim3 blk(256);
    esplit_kernel<<<dim3(ROWS * EMBED / 256), blk>>>(tok, emb);
    w1split_kernel<<<dim3(HIDDEN * EMBED / 256), blk>>>(W1);
    wsplit_kernel<<<dim3(HIDDEN * HIDDEN / 256, 1, 3), blk>>>(Wq, Wk, Wv);
    embed_mma_kernel<<<dim3(HIDDEN / 128, ROWS / 128), blk, SMEM_BYTES>>>(b1);
    qkv_mma_kernel<<<dim3(HIDDEN / 128, ROWS / 128, 3), blk, SMEM_BYTES>>>(bq, bk, bv);
    scores_mma_kernel<<<dim3(SEQ / 128, SEQ / 128, BATCH), blk, SMEM_BYTES>>>();
    softmax_kernel<<<dim3(ROWS), blk>>>();
    out_mma_kernel<<<dim3(HIDDEN / 128, SEQ / 128, BATCH), blk, SMEM_BYTES>>>(out);
}

// round 15
// speedup vs baseline: 1.1214x; 1.0065x over previous
#include <cuda_runtime.h>
#include <cuda_bf16.h>
#include <math.h>
#include <stdint.h>

#define BATCH  4
#define SEQ    2048
#define EMBED  256
#define HIDDEN 512
#define ROWS   (BATCH * SEQ)   // 8192

// -------- scratch (allocation-free: __device__ globals) --------
__device__ __align__(16) __nv_bfloat16 g_eh[ROWS * EMBED];               // 4 MB gathered emb hi
__device__ __align__(16) __nv_bfloat16 g_el[ROWS * EMBED];
__device__ __align__(16) __nv_bfloat16 g_w1h[HIDDEN * EMBED];            // W1^T hi [n][k]
__device__ __align__(16) __nv_bfloat16 g_w1l[HIDDEN * EMBED];
__device__ __align__(16) __nv_bfloat16 g_acth[ROWS * HIDDEN];            // 8 MB
__device__ __align__(16) __nv_bfloat16 g_actl[ROWS * HIDDEN];
__device__ __align__(16) __nv_bfloat16 g_wth[3 * HIDDEN * HIDDEN];       // W^T hi  [z][n][k]
__device__ __align__(16) __nv_bfloat16 g_wtl[3 * HIDDEN * HIDDEN];
__device__ __align__(16) __nv_bfloat16 g_qh[ROWS * HIDDEN];
__device__ __align__(16) __nv_bfloat16 g_ql[ROWS * HIDDEN];
__device__ __align__(16) __nv_bfloat16 g_kh[ROWS * HIDDEN];
__device__ __align__(16) __nv_bfloat16 g_kl[ROWS * HIDDEN];
__device__ __align__(16) __nv_bfloat16 g_vth[BATCH * HIDDEN * SEQ];      // V^T [b][h][s]
__device__ __align__(16) __nv_bfloat16 g_vtl[BATCH * HIDDEN * SEQ];
__device__ float g_scores[(size_t)BATCH * SEQ * SEQ];                    // 64 MB
__device__ __align__(16) __nv_bfloat16 g_ah[(size_t)BATCH * SEQ * SEQ];  // attn hi
__device__ __align__(16) __nv_bfloat16 g_al[(size_t)BATCH * SEQ * SEQ];  // attn lo

__device__ __forceinline__ void bf16_split(float x, __nv_bfloat16& h, __nv_bfloat16& l) {
    h = __float2bfloat16_rn(x);
    l = __float2bfloat16_rn(x - __bfloat162float(h));
}

// ============================================================
// Prep kernels: gather/split emb rows; transpose+split weights
// ============================================================
__global__ void esplit_kernel(const int* __restrict__ tok,
                              const float* __restrict__ emb)
{
    int idx = blockIdx.x * 256 + threadIdx.x;       // over ROWS*EMBED
    int row = idx >> 8, col = idx & 255;
    int token = tok[row];
    float x = emb[(size_t)token * EMBED + col];
    __nv_bfloat16 h, l;
    bf16_split(x, h, l);
    g_eh[idx] = h; g_el[idx] = l;
}

__global__ void w1split_kernel(const float* __restrict__ W1)
{
    int idx = blockIdx.x * 256 + threadIdx.x;       // over HIDDEN*EMBED
    int n = idx >> 8, k = idx & 255;
    float x = W1[k * HIDDEN + n];
    __nv_bfloat16 h, l;
    bf16_split(x, h, l);
    g_w1h[idx] = h; g_w1l[idx] = l;
}

__global__ void wsplit_kernel(const float* __restrict__ Wq,
                              const float* __restrict__ Wk,
                              const float* __restrict__ Wv)
{
    const int z = blockIdx.z;
    const float* W = (z == 0) ? Wq : (z == 1) ? Wk : Wv;
    int idx = blockIdx.x * 256 + threadIdx.x;       // over 512*512
    int n = idx >> 9, k = idx & 511;
    float x = W[k * HIDDEN + n];
    __nv_bfloat16 h, l;
    bf16_split(x, h, l);
    size_t o = (size_t)z * HIDDEN * HIDDEN + (size_t)n * HIDDEN + k;
    g_wth[o] = h; g_wtl[o] = l;
}

// ============================================================
// Warp-MMA GEMM core (mma.sync m16n8k16 bf16 hi/lo split),
// 2-stage cp.async pipeline + full LDSM/MMA interleave with
// cross-k16-step fragment prefetch (one serial head per stage).
// C tile 128x128, 8 warps (2m x 4n), warp tile 64x32, KC=32.
// ============================================================
#define KC          32
#define SPITCH      40
#define TILE_ELEMS  (128 * SPITCH)          // per tile, bf16 elems
#define STAGE_ELEMS (4 * TILE_ELEMS)
#define SMEM_BYTES  (2 * STAGE_ELEMS * 2)   // 81920

extern __shared__ __nv_bfloat16 dsm[];

__device__ __forceinline__ uint32_t smem_u32(const void* p) {
    uint32_t a;
    asm("{ .reg .u64 t; cvta.to.shared.u64 t, %1; cvt.u32.u64 %0, t; }" : "=r"(a) : "l"(p));
    return a;
}
__device__ __forceinline__ void cp16(uint32_t dst, const void* src) {
    asm volatile("cp.async.cg.shared.global [%0], [%1], 16;" :: "r"(dst), "l"(src));
}
__device__ __forceinline__ void cp_commit() {
    asm volatile("cp.async.commit_group;" ::: "memory");
}
template <int N>
__device__ __forceinline__ void cp_wait() {
    asm volatile("cp.async.wait_group %0;" :: "n"(N) : "memory");
}

__device__ __forceinline__ void mma16816(float c[4], const uint32_t a[4], const uint32_t b[2]) {
    asm volatile(
        "mma.sync.aligned.m16n8k16.row.col.f32.bf16.bf16.f32 "
        "{%0,%1,%2,%3}, {%4,%5,%6,%7}, {%8,%9}, {%0,%1,%2,%3};"
        : "+f"(c[0]), "+f"(c[1]), "+f"(c[2]), "+f"(c[3])
        : "r"(a[0]), "r"(a[1]), "r"(a[2]), "r"(a[3]), "r"(b[0]), "r"(b[1]));
}

__device__ __forceinline__ void ldsm4(uint32_t r[4], uint32_t addr) {
    asm volatile("ldmatrix.sync.aligned.m8n8.x4.shared.b16 {%0,%1,%2,%3}, [%4];"
                 : "=r"(r[0]), "=r"(r[1]), "=r"(r[2]), "=r"(r[3]) : "r"(addr));
}

// fragment loaders (ldmatrix x4; per-lane mapping validated R12)
__device__ __forceinline__ void load_afrag(uint32_t base, int kk, int wm,
                                           uint32_t a_off, uint32_t f[4][4]) {
    #pragma unroll
    for (int mi = 0; mi < 4; mi++) {
        uint32_t ro = (uint32_t)((wm + mi * 16) * SPITCH + kk) * 2;
        ldsm4(f[mi], base + a_off + ro);
    }
}
__device__ __forceinline__ void load_bfrag(uint32_t base, int kk, int wn,
                                           uint32_t b_off, uint32_t f[4][2]) {
    #pragma unroll
    for (int np = 0; np < 2; np++) {
        uint32_t ro = (uint32_t)((wn + np * 16) * SPITCH + kk) * 2;
        uint32_t r[4];
        ldsm4(r, base + b_off + ro);
        f[np * 2][0] = r[0]; f[np * 2][1] = r[1];
        f[np * 2 + 1][0] = r[2]; f[np * 2 + 1][1] = r[3];
    }
}

// async copy of one 128x32 bf16 tile into padded smem tile
__device__ __forceinline__ void copy_tile_async(const __nv_bfloat16* __restrict__ src,
                                                size_t ld, uint32_t dst, int t)
{
    #pragma unroll
    for (int i = 0; i < 2; i++) {
        int idx = t + i * 256;
        int r = idx >> 2, c = idx & 3;
        cp16(dst + (uint32_t)(r * SPITCH + c * 8) * 2,
             src + (size_t)r * ld + c * 8);
    }
}

template <class Epi>
__device__ __forceinline__ void gemm_mma_body(
    const __nv_bfloat16* __restrict__ Ah, const __nv_bfloat16* __restrict__ Al, size_t lda,
    const __nv_bfloat16* __restrict__ Bh, const __nv_bfloat16* __restrict__ Bl, size_t ldb,
    int K, Epi epi)
{
    const int t    = threadIdx.x;
    const int lane = t & 31;
    const int wid  = t >> 5;
    const int wm   = (wid & 1) * 64;      // warp m-offset
    const int wn   = (wid >> 1) * 32;     // warp n-offset
    const int g    = lane >> 2;
    const int tg   = lane & 3;

    const int lr = lane & 7, q = lane >> 3;
    const uint32_t a_off = (uint32_t)(((lr + (q & 1) * 8) * SPITCH) + (q & 2) * 4) * 2;
    const uint32_t b_off = (uint32_t)(((lr + (q & 2) * 4) * SPITCH) + (q & 1) * 8) * 2;

    const uint32_t sbase = smem_u32(dsm);
    const int kTiles = K / KC;

    float acc[4][4][4] = {};

    // prologue: prefetch stage 0
    {
        uint32_t st = sbase;
        copy_tile_async(Ah, lda, st,                       t);
        copy_tile_async(Al, lda, st + TILE_ELEMS * 2,      t);
        copy_tile_async(Bh, ldb, st + 2 * TILE_ELEMS * 2,  t);
        copy_tile_async(Bl, ldb, st + 3 * TILE_ELEMS * 2,  t);
        cp_commit();
    }

    int s = 0;
    for (int kb = 0; kb < kTiles; kb++) {
        if (kb + 1 < kTiles) {
            const size_t ko = (size_t)(kb + 1) * KC;
            uint32_t st = sbase + (uint32_t)((s ^ 1) * STAGE_ELEMS) * 2;
            copy_tile_async(Ah + ko, lda, st,                      t);
            copy_tile_async(Al + ko, lda, st + TILE_ELEMS * 2,     t);
            copy_tile_async(Bh + ko, ldb, st + 2 * TILE_ELEMS * 2, t);
            copy_tile_async(Bl + ko, ldb, st + 3 * TILE_ELEMS * 2, t);
            cp_commit();
            cp_wait<1>();
        } else {
            cp_wait<0>();
        }
        __syncthreads();

        const uint32_t stb = sbase + (uint32_t)(s * STAGE_ELEMS) * 2;
        const uint32_t aH = stb;
        const uint32_t aL = stb + TILE_ELEMS * 2;
        const uint32_t bH = stb + 2 * TILE_ELEMS * 2;
        const uint32_t bL = stb + 3 * TILE_ELEMS * 2;

        uint32_t ah0[4][4], bh0[4][2], al[4][4], bl[4][2];
        uint32_t ah1[4][4], bh1[4][2];

        // ---- serial head (once per stage): hi fragments for kk=0 ----
        load_afrag(aH, 0, wm, a_off, ah0);
        load_bfrag(bH, 0, wn, b_off, bh0);

        // ================= kk = 0 =================
        // hh pass, first half + al load under cover
        #pragma unroll
        for (int mi = 0; mi < 2; mi++)
            #pragma unroll
            for (int ni = 0; ni < 4; ni++)
                mma16816(acc[mi][ni], ah0[mi], bh0[ni]);
        load_afrag(aL, 0, wm, a_off, al);
        #pragma unroll
        for (int mi = 2; mi < 4; mi++)
            #pragma unroll
            for (int ni = 0; ni < 4; ni++)
                mma16816(acc[mi][ni], ah0[mi], bh0[ni]);
        load_bfrag(bL, 0, wn, b_off, bl);
        // lh pass
        #pragma unroll
        for (int mi = 0; mi < 4; mi++)
            #pragma unroll
            for (int ni = 0; ni < 4; ni++)
                mma16816(acc[mi][ni], al[mi], bh0[ni]);
        // hl pass + prefetch kk=16 hi fragments (al/bh0 dead -> regs reused)
        #pragma unroll
        for (int mi = 0; mi < 2; mi++)
            #pragma unroll
            for (int ni = 0; ni < 4; ni++)
                mma16816(acc[mi][ni], ah0[mi], bl[ni]);
        load_afrag(aH, 16, wm, a_off, ah1);
        load_bfrag(bH, 16, wn, b_off, bh1);
        #pragma unroll
        for (int mi = 2; mi < 4; mi++)
            #pragma unroll
            for (int ni = 0; ni < 4; ni++)
                mma16816(acc[mi][ni], ah0[mi], bl[ni]);

        // ================= kk = 16 =================
        #pragma unroll
        for (int mi = 0; mi < 2; mi++)
            #pragma unroll
            for (int ni = 0; ni < 4; ni++)
                mma16816(acc[mi][ni], ah1[mi], bh1[ni]);
        load_afrag(aL, 16, wm, a_off, al);
        #pragma unroll
        for (int mi = 2; mi < 4; mi++)
            #pragma unroll
            for (int ni = 0; ni < 4; ni++)
                mma16816(acc[mi][ni], ah1[mi], bh1[ni]);
        load_bfrag(bL, 16, wn, b_off, bl);
        #pragma unroll
        for (int mi = 0; mi < 4; mi++)
            #pragma unroll
            for (int ni = 0; ni < 4; ni++)
                mma16816(acc[mi][ni], al[mi], bh1[ni]);
        #pragma unroll
        for (int mi = 0; mi < 4; mi++)
            #pragma unroll
            for (int ni = 0; ni < 4; ni++)
                mma16816(acc[mi][ni], ah1[mi], bl[ni]);

        __syncthreads();
        s ^= 1;
    }

    #pragma unroll
    for (int mi = 0; mi < 4; mi++)
        #pragma unroll
        for (int ni = 0; ni < 4; ni++) {
            int r0 = wm + mi * 16 + g;
            int c0 = wn + ni * 8 + tg * 2;
            epi(r0,     c0,     acc[mi][ni][0]);
            epi(r0,     c0 + 1, acc[mi][ni][1]);
            epi(r0 + 8, c0,     acc[mi][ni][2]);
            epi(r0 + 8, c0 + 1, acc[mi][ni][3]);
        }
}

// ============================================================
// Kernel 1: act = gelu( emb @ W1 + b1 )  (warp MMA over split emb)
// ============================================================
__global__ void __launch_bounds__(256, 2) embed_mma_kernel(const float* __restrict__ b1)
{
    const int tile_n = blockIdx.x * 128;
    const int tile_m = blockIdx.y * 128;
    const __nv_bfloat16* Ah = g_eh + (size_t)tile_m * EMBED;
    const __nv_bfloat16* Al = g_el + (size_t)tile_m * EMBED;
    const __nv_bfloat16* Bh = g_w1h + (size_t)tile_n * EMBED;
    const __nv_bfloat16* Bl = g_w1l + (size_t)tile_n * EMBED;

    gemm_mma_body(Ah, Al, EMBED, Bh, Bl, EMBED, EMBED,
        [&](int r, int c, float v) {
            int row = tile_m + r, col = tile_n + c;
            float x = v + b1[col];
            float gl = 0.5f * x * (1.0f + erff(x * 0.7071067811865475f));
            __nv_bfloat16 h, l;
            bf16_split(gl, h, l);
            size_t o = (size_t)row * HIDDEN + col;
            g_acth[o] = h; g_actl[o] = l;
        });
}

// ============================================================
// Kernel 2: q/k/v = act @ W + b  (warp MMA), epi splits hi/lo (V transposed)
// ============================================================
__global__ void __launch_bounds__(256, 2) qkv_mma_kernel(const float* __restrict__ bq,
                                                         const float* __restrict__ bk,
                                                         const float* __restrict__ bv)
{
    const int z = blockIdx.z;
    const int tile_n = blockIdx.x * 128;
    const int tile_m = blockIdx.y * 128;
    const float* bias = (z == 0) ? bq : (z == 1) ? bk : bv;

    const __nv_bfloat16* Ah = g_acth + (size_t)tile_m * HIDDEN;
    const __nv_bfloat16* Al = g_actl + (size_t)tile_m * HIDDEN;
    const __nv_bfloat16* Bh = g_wth + (size_t)z * HIDDEN * HIDDEN + (size_t)tile_n * HIDDEN;
    const __nv_bfloat16* Bl = g_wtl + (size_t)z * HIDDEN * HIDDEN + (size_t)tile_n * HIDDEN;

    gemm_mma_body(Ah, Al, HIDDEN, Bh, Bl, HIDDEN, HIDDEN,
        [&](int r, int c, float v) {
            int row = tile_m + r, col = tile_n + c;
            float x = v + bias[col];
            __nv_bfloat16 h, l;
            bf16_split(x, h, l);
            if (z == 2) {
                int b = row >> 11, s = row & (SEQ - 1);
                size_t o = ((size_t)b * HIDDEN + col) * SEQ + s;
                g_vth[o] = h; g_vtl[o] = l;
            } else {
                size_t o = (size_t)row * HIDDEN + col;
                if (z == 0) { g_qh[o] = h; g_ql[o] = l; }
                else        { g_kh[o] = h; g_kl[o] = l; }
            }
        });
}

// ============================================================
// Kernel 3: scores = (Q @ K^T) / sqrt(512)  (warp MMA)
// ============================================================
__global__ void __launch_bounds__(256, 2) scores_mma_kernel()
{
    const int z = blockIdx.z;
    const int tile_n = blockIdx.x * 128;
    const int tile_m = blockIdx.y * 128;
    const __nv_bfloat16* Ah = g_qh + ((size_t)z * SEQ + tile_m) * HIDDEN;
    const __nv_bfloat16* Al = g_ql + ((size_t)z * SEQ + tile_m) * HIDDEN;
    const __nv_bfloat16* Bh = g_kh + ((size_t)z * SEQ + tile_n) * HIDDEN;
    const __nv_bfloat16* Bl = g_kl + ((size_t)z * SEQ + tile_n) * HIDDEN;
    float* C = g_scores + (size_t)z * SEQ * SEQ + (size_t)tile_m * SEQ + tile_n;
    const float scale = 0.04419417382415922f;   // 1/sqrt(512)

    gemm_mma_body(Ah, Al, HIDDEN, Bh, Bl, HIDDEN, HIDDEN,
        [&](int r, int c, float v) {
            C[(size_t)r * SEQ + c] = v * scale;
        });
}

// ============================================================
// Kernel 4: row softmax; writes attn bf16 hi/lo
// ============================================================
__global__ void softmax_kernel()
{
    const int row = blockIdx.x;
    const float* p = g_scores + (size_t)row * SEQ;
    __nv_bfloat16* oh = g_ah + (size_t)row * SEQ;
    __nv_bfloat16* ol = g_al + (size_t)row * SEQ;
    const int t = threadIdx.x;
    __shared__ float red[16];

    float v[8];
    float lmax = -1e30f;
    #pragma unroll
    for (int i = 0; i < 8; i++) {
        v[i] = p[t + i * 256];
        lmax = fmaxf(lmax, v[i]);
    }
    #pragma unroll
    for (int o = 16; o; o >>= 1)
        lmax = fmaxf(lmax, __shfl_xor_sync(0xffffffffu, lmax, o));
    if ((t & 31) == 0) red[t >> 5] = lmax;
    __syncthreads();
    float rmax = red[0];
    #pragma unroll
    for (int i = 1; i < 8; i++) rmax = fmaxf(rmax, red[i]);

    float lsum = 0.0f;
    #pragma unroll
    for (int i = 0; i < 8; i++) {
        v[i] = __expf(v[i] - rmax);
        lsum += v[i];
    }
    #pragma unroll
    for (int o = 16; o; o >>= 1)
        lsum += __shfl_xor_sync(0xffffffffu, lsum, o);
    if ((t & 31) == 0) red[8 + (t >> 5)] = lsum;
    __syncthreads();
    float total = 0.0f;
    #pragma unroll
    for (int i = 0; i < 8; i++) total += red[8 + i];

    float inv = 1.0f / total;
    #pragma unroll
    for (int i = 0; i < 8; i++) {
        float pr = v[i] * inv;
        __nv_bfloat16 h, l;
        bf16_split(pr, h, l);
        oh[t + i * 256] = h;
        ol[t + i * 256] = l;
    }
}

// ============================================================
// Kernel 5: out = attn @ V  (warp MMA, B = V^T K-major over tokens)
// ============================================================
__global__ void __launch_bounds__(256, 2) out_mma_kernel(float* __restrict__ out)
{
    const int z = blockIdx.z;
    const int tile_n = blockIdx.x * 128;   // head dim
    const int tile_m = blockIdx.y * 128;   // query pos
    const __nv_bfloat16* Ah = g_ah + (size_t)z * SEQ * SEQ + (size_t)tile_m * SEQ;
    const __nv_bfloat16* Al = g_al + (size_t)z * SEQ * SEQ + (size_t)tile_m * SEQ;
    const __nv_bfloat16* Bh = g_vth + ((size_t)z * HIDDEN + tile_n) * SEQ;
    const __nv_bfloat16* Bl = g_vtl + ((size_t)z * HIDDEN + tile_n) * SEQ;
    float* C = out + ((size_t)z * SEQ + tile_m) * HIDDEN + tile_n;

    gemm_mma_body(Ah, Al, SEQ, Bh, Bl, SEQ, SEQ,
        [&](int r, int c, float v) {
            C[(size_t)r * HIDDEN + c] = v;
        });
}

// ============================================================
// launch
// ============================================================
extern "C" void kernel_launch(void* const* d_in, const int* in_sizes, int n_in,
                              void* d_out, int out_size)
{
    const int*   tok = (const int*)  d_in[0];
    const float* emb = (const float*)d_in[1];
    const float* W1  = (const float*)d_in[2];
    const float* b1  = (const float*)d_in[3];
    const float* Wq  = (const float*)d_in[4];
    const float* bq  = (const float*)d_in[5];
    const float* Wk  = (const float*)d_in[6];
    const float* bk  = (const float*)d_in[7];
    const float* Wv  = (const float*)d_in[8];
    const float* bv  = (const float*)d_in[9];
    float* out = (float*)d_out;

    static int smem_set = 0;
    if (!smem_set) {
        (void)cudaFuncSetAttribute(embed_mma_kernel,
                                   cudaFuncAttributeMaxDynamicSharedMemorySize, SMEM_BYTES);
        (void)cudaFuncSetAttribute(qkv_mma_kernel,
                                   cudaFuncAttributeMaxDynamicSharedMemorySize, SMEM_BYTES);
        (void)cudaFuncSetAttribute(scores_mma_kernel,
                                   cudaFuncAttributeMaxDynamicSharedMemorySize, SMEM_BYTES);
        (void)cudaFuncSetAttribute(out_mma_kernel,
                                   cudaFuncAttributeMaxDynamicSharedMemorySize, SMEM_BYTES);
        smem_set = 1;
    }

    dim3 blk(256);
    esplit_kernel<<<dim3(ROWS * EMBED / 256), blk>>>(tok, emb);
    w1split_kernel<<<dim3(HIDDEN * EMBED / 256), blk>>>(W1);
    wsplit_kernel<<<dim3(HIDDEN * HIDDEN / 256, 1, 3), blk>>>(Wq, Wk, Wv);
    embed_mma_kernel<<<dim3(HIDDEN / 128, ROWS / 128), blk, SMEM_BYTES>>>(b1);
    qkv_mma_kernel<<<dim3(HIDDEN / 128, ROWS / 128, 3), blk, SMEM_BYTES>>>(bq, bk, bv);
    scores_mma_kernel<<<dim3(SEQ / 128, SEQ / 128, BATCH), blk, SMEM_BYTES>>>();
    softmax_kernel<<<dim3(ROWS), blk>>>();
    out_mma_kernel<<<dim3(HIDDEN / 128, SEQ / 128, BATCH), blk, SMEM_BYTES>>>(out);
}

// round 16
// speedup vs baseline: 1.4593x; 1.3013x over previous
#include <cuda_runtime.h>
#include <cuda_fp16.h>
#include <math.h>
#include <stdint.h>

#define BATCH  4
#define SEQ    2048
#define EMBED  256
#define HIDDEN 512
#define ROWS   (BATCH * SEQ)   // 8192

// -------- scratch (allocation-free: __device__ globals) --------
// A-side operands carry hi+lo fp16; B-side operands carry hi only.
__device__ __align__(16) __half g_eh[ROWS * EMBED];                // emb gathered hi
__device__ __align__(16) __half g_el[ROWS * EMBED];
__device__ __align__(16) __half g_w1h[HIDDEN * EMBED];             // W1^T hi [n][k]
__device__ __align__(16) __half g_acth[ROWS * HIDDEN];
__device__ __align__(16) __half g_actl[ROWS * HIDDEN];
__device__ __align__(16) __half g_wth[3 * HIDDEN * HIDDEN];        // W^T hi [z][n][k]
__device__ __align__(16) __half g_qh[ROWS * HIDDEN];
__device__ __align__(16) __half g_ql[ROWS * HIDDEN];
__device__ __align__(16) __half g_kh[ROWS * HIDDEN];               // k hi only (B side)
__device__ __align__(16) __half g_vth[BATCH * HIDDEN * SEQ];       // V^T hi [b][h][s]
__device__ float g_scores[(size_t)BATCH * SEQ * SEQ];              // 64 MB
__device__ __align__(16) __half g_ah[(size_t)BATCH * SEQ * SEQ];   // attn hi
__device__ __align__(16) __half g_al[(size_t)BATCH * SEQ * SEQ];   // attn lo

__device__ __forceinline__ void f16_split(float x, __half& h, __half& l) {
    h = __float2half_rn(x);
    l = __float2half_rn(x - __half2float(h));
}

// ============================================================
// Prep kernels
// ============================================================
__global__ void esplit_kernel(const int* __restrict__ tok,
                              const float* __restrict__ emb)
{
    int idx = blockIdx.x * 256 + threadIdx.x;       // over ROWS*EMBED
    int row = idx >> 8, col = idx & 255;
    int token = tok[row];
    float x = emb[(size_t)token * EMBED + col];
    __half h, l;
    f16_split(x, h, l);
    g_eh[idx] = h; g_el[idx] = l;
}

__global__ void w1split_kernel(const float* __restrict__ W1)
{
    int idx = blockIdx.x * 256 + threadIdx.x;       // over HIDDEN*EMBED
    int n = idx >> 8, k = idx & 255;
    g_w1h[idx] = __float2half_rn(W1[k * HIDDEN + n]);
}

__global__ void wsplit_kernel(const float* __restrict__ Wq,
                              const float* __restrict__ Wk,
                              const float* __restrict__ Wv)
{
    const int z = blockIdx.z;
    const float* W = (z == 0) ? Wq : (z == 1) ? Wk : Wv;
    int idx = blockIdx.x * 256 + threadIdx.x;       // over 512*512
    int n = idx >> 9, k = idx & 511;
    g_wth[(size_t)z * HIDDEN * HIDDEN + idx] = __float2half_rn(W[k * HIDDEN + n]);
}

// ============================================================
// Warp-MMA GEMM core: fp16 2-pass split (A = Ah+Al, B = Bh),
// mma.sync m16n8k16 f32.f16.f16.f32, 2-stage cp.async pipeline,
// ldmatrix fragment loads with cross-k16-step prefetch.
// C tile 128x128, 8 warps (2m x 4n), warp tile 64x32, KC=32.
// Smem: 2 stages x 3 tiles x [128][40] half = 61440 B.
// ============================================================
#define KC          32
#define SPITCH      40
#define TILE_ELEMS  (128 * SPITCH)
#define STAGE_ELEMS (3 * TILE_ELEMS)
#define SMEM_BYTES  (2 * STAGE_ELEMS * 2)   // 61440

extern __shared__ __half dsm[];

__device__ __forceinline__ uint32_t smem_u32(const void* p) {
    uint32_t a;
    asm("{ .reg .u64 t; cvta.to.shared.u64 t, %1; cvt.u32.u64 %0, t; }" : "=r"(a) : "l"(p));
    return a;
}
__device__ __forceinline__ void cp16(uint32_t dst, const void* src) {
    asm volatile("cp.async.cg.shared.global [%0], [%1], 16;" :: "r"(dst), "l"(src));
}
__device__ __forceinline__ void cp_commit() {
    asm volatile("cp.async.commit_group;" ::: "memory");
}
template <int N>
__device__ __forceinline__ void cp_wait() {
    asm volatile("cp.async.wait_group %0;" :: "n"(N) : "memory");
}

__device__ __forceinline__ void mma16816(float c[4], const uint32_t a[4], const uint32_t b[2]) {
    asm volatile(
        "mma.sync.aligned.m16n8k16.row.col.f32.f16.f16.f32 "
        "{%0,%1,%2,%3}, {%4,%5,%6,%7}, {%8,%9}, {%0,%1,%2,%3};"
        : "+f"(c[0]), "+f"(c[1]), "+f"(c[2]), "+f"(c[3])
        : "r"(a[0]), "r"(a[1]), "r"(a[2]), "r"(a[3]), "r"(b[0]), "r"(b[1]));
}

__device__ __forceinline__ void ldsm4(uint32_t r[4], uint32_t addr) {
    asm volatile("ldmatrix.sync.aligned.m8n8.x4.shared.b16 {%0,%1,%2,%3}, [%4];"
                 : "=r"(r[0]), "=r"(r[1]), "=r"(r[2]), "=r"(r[3]) : "r"(addr));
}

__device__ __forceinline__ void load_afrag(uint32_t base, int kk, int wm,
                                           uint32_t a_off, uint32_t f[4][4]) {
    #pragma unroll
    for (int mi = 0; mi < 4; mi++) {
        uint32_t ro = (uint32_t)((wm + mi * 16) * SPITCH + kk) * 2;
        ldsm4(f[mi], base + a_off + ro);
    }
}
__device__ __forceinline__ void load_bfrag(uint32_t base, int kk, int wn,
                                           uint32_t b_off, uint32_t f[4][2]) {
    #pragma unroll
    for (int np = 0; np < 2; np++) {
        uint32_t ro = (uint32_t)((wn + np * 16) * SPITCH + kk) * 2;
        uint32_t r[4];
        ldsm4(r, base + b_off + ro);
        f[np * 2][0] = r[0]; f[np * 2][1] = r[1];
        f[np * 2 + 1][0] = r[2]; f[np * 2 + 1][1] = r[3];
    }
}

// async copy of one 128x32 half tile into padded smem tile
__device__ __forceinline__ void copy_tile_async(const __half* __restrict__ src,
                                                size_t ld, uint32_t dst, int t)
{
    #pragma unroll
    for (int i = 0; i < 2; i++) {
        int idx = t + i * 256;
        int r = idx >> 2, c = idx & 3;
        cp16(dst + (uint32_t)(r * SPITCH + c * 8) * 2,
             src + (size_t)r * ld + c * 8);
    }
}

template <class Epi>
__device__ __forceinline__ void gemm_mma_body(
    const __half* __restrict__ Ah, const __half* __restrict__ Al, size_t lda,
    const __half* __restrict__ Bh, size_t ldb,
    int K, Epi epi)
{
    const int t    = threadIdx.x;
    const int lane = t & 31;
    const int wid  = t >> 5;
    const int wm   = (wid & 1) * 64;      // warp m-offset
    const int wn   = (wid >> 1) * 32;     // warp n-offset
    const int g    = lane >> 2;
    const int tg   = lane & 3;

    const int lr = lane & 7, q = lane >> 3;
    const uint32_t a_off = (uint32_t)(((lr + (q & 1) * 8) * SPITCH) + (q & 2) * 4) * 2;
    const uint32_t b_off = (uint32_t)(((lr + (q & 2) * 4) * SPITCH) + (q & 1) * 8) * 2;

    const uint32_t sbase = smem_u32(dsm);
    const int kTiles = K / KC;

    float acc[4][4][4] = {};

    // prologue: prefetch stage 0 (3 tiles)
    {
        uint32_t st = sbase;
        copy_tile_async(Ah, lda, st,                      t);
        copy_tile_async(Al, lda, st + TILE_ELEMS * 2,     t);
        copy_tile_async(Bh, ldb, st + 2 * TILE_ELEMS * 2, t);
        cp_commit();
    }

    int s = 0;
    for (int kb = 0; kb < kTiles; kb++) {
        if (kb + 1 < kTiles) {
            const size_t ko = (size_t)(kb + 1) * KC;
            uint32_t st = sbase + (uint32_t)((s ^ 1) * STAGE_ELEMS) * 2;
            copy_tile_async(Ah + ko, lda, st,                      t);
            copy_tile_async(Al + ko, lda, st + TILE_ELEMS * 2,     t);
            copy_tile_async(Bh + ko, ldb, st + 2 * TILE_ELEMS * 2, t);
            cp_commit();
            cp_wait<1>();
        } else {
            cp_wait<0>();
        }
        __syncthreads();

        const uint32_t stb = sbase + (uint32_t)(s * STAGE_ELEMS) * 2;
        const uint32_t aH = stb;
        const uint32_t aL = stb + TILE_ELEMS * 2;
        const uint32_t bH = stb + 2 * TILE_ELEMS * 2;

        uint32_t ah0[4][4], bh0[4][2], al[4][4];
        uint32_t ah1[4][4], bh1[4][2];

        // ---- serial head (once per stage): hi fragments for kk=0 ----
        load_afrag(aH, 0, wm, a_off, ah0);
        load_bfrag(bH, 0, wn, b_off, bh0);

        // ================= kk = 0 =================
        #pragma unroll
        for (int mi = 0; mi < 2; mi++)
            #pragma unroll
            for (int ni = 0; ni < 4; ni++)
                mma16816(acc[mi][ni], ah0[mi], bh0[ni]);
        load_afrag(aL, 0, wm, a_off, al);           // al under hh cover
        #pragma unroll
        for (int mi = 2; mi < 4; mi++)
            #pragma unroll
            for (int ni = 0; ni < 4; ni++)
                mma16816(acc[mi][ni], ah0[mi], bh0[ni]);
        // lh pass + prefetch kk=16 hi fragments under cover (ah0 dead)
        #pragma unroll
        for (int mi = 0; mi < 2; mi++)
            #pragma unroll
            for (int ni = 0; ni < 4; ni++)
                mma16816(acc[mi][ni], al[mi], bh0[ni]);
        load_afrag(aH, 16, wm, a_off, ah1);
        load_bfrag(bH, 16, wn, b_off, bh1);
        #pragma unroll
        for (int mi = 2; mi < 4; mi++)
            #pragma unroll
            for (int ni = 0; ni < 4; ni++)
                mma16816(acc[mi][ni], al[mi], bh0[ni]);

        // ================= kk = 16 =================
        #pragma unroll
        for (int mi = 0; mi < 2; mi++)
            #pragma unroll
            for (int ni = 0; ni < 4; ni++)
                mma16816(acc[mi][ni], ah1[mi], bh1[ni]);
        load_afrag(aL, 16, wm, a_off, al);          // al under hh cover
        #pragma unroll
        for (int mi = 2; mi < 4; mi++)
            #pragma unroll
            for (int ni = 0; ni < 4; ni++)
                mma16816(acc[mi][ni], ah1[mi], bh1[ni]);
        #pragma unroll
        for (int mi = 0; mi < 4; mi++)
            #pragma unroll
            for (int ni = 0; ni < 4; ni++)
                mma16816(acc[mi][ni], al[mi], bh1[ni]);

        __syncthreads();
        s ^= 1;
    }

    #pragma unroll
    for (int mi = 0; mi < 4; mi++)
        #pragma unroll
        for (int ni = 0; ni < 4; ni++) {
            int r0 = wm + mi * 16 + g;
            int c0 = wn + ni * 8 + tg * 2;
            epi(r0,     c0,     acc[mi][ni][0]);
            epi(r0,     c0 + 1, acc[mi][ni][1]);
            epi(r0 + 8, c0,     acc[mi][ni][2]);
            epi(r0 + 8, c0 + 1, acc[mi][ni][3]);
        }
}

// ============================================================
// Kernel 1: act = gelu( emb @ W1 + b1 )
// ============================================================
__global__ void __launch_bounds__(256, 2) embed_mma_kernel(const float* __restrict__ b1)
{
    const int tile_n = blockIdx.x * 128;
    const int tile_m = blockIdx.y * 128;
    const __half* Ah = g_eh + (size_t)tile_m * EMBED;
    const __half* Al = g_el + (size_t)tile_m * EMBED;
    const __half* Bh = g_w1h + (size_t)tile_n * EMBED;

    gemm_mma_body(Ah, Al, EMBED, Bh, EMBED, EMBED,
        [&](int r, int c, float v) {
            int row = tile_m + r, col = tile_n + c;
            float x = v + b1[col];
            float gl = 0.5f * x * (1.0f + erff(x * 0.7071067811865475f));
            __half h, l;
            f16_split(gl, h, l);
            size_t o = (size_t)row * HIDDEN + col;
            g_acth[o] = h; g_actl[o] = l;
        });
}

// ============================================================
// Kernel 2: q/k/v = act @ W + b  (q hi/lo; k hi; v^T hi)
// ============================================================
__global__ void __launch_bounds__(256, 2) qkv_mma_kernel(const float* __restrict__ bq,
                                                         const float* __restrict__ bk,
                                                         const float* __restrict__ bv)
{
    const int z = blockIdx.z;
    const int tile_n = blockIdx.x * 128;
    const int tile_m = blockIdx.y * 128;
    const float* bias = (z == 0) ? bq : (z == 1) ? bk : bv;

    const __half* Ah = g_acth + (size_t)tile_m * HIDDEN;
    const __half* Al = g_actl + (size_t)tile_m * HIDDEN;
    const __half* Bh = g_wth + (size_t)z * HIDDEN * HIDDEN + (size_t)tile_n * HIDDEN;

    gemm_mma_body(Ah, Al, HIDDEN, Bh, HIDDEN, HIDDEN,
        [&](int r, int c, float v) {
            int row = tile_m + r, col = tile_n + c;
            float x = v + bias[col];
            if (z == 0) {
                __half h, l;
                f16_split(x, h, l);
                size_t o = (size_t)row * HIDDEN + col;
                g_qh[o] = h; g_ql[o] = l;
            } else if (z == 1) {
                g_kh[(size_t)row * HIDDEN + col] = __float2half_rn(x);
            } else {
                int b = row >> 11, sq = row & (SEQ - 1);
                g_vth[((size_t)b * HIDDEN + col) * SEQ + sq] = __float2half_rn(x);
            }
        });
}

// ============================================================
// Kernel 3: scores = (Q @ K^T) / sqrt(512)
// ============================================================
__global__ void __launch_bounds__(256, 2) scores_mma_kernel()
{
    const int z = blockIdx.z;
    const int tile_n = blockIdx.x * 128;
    const int tile_m = blockIdx.y * 128;
    const __half* Ah = g_qh + ((size_t)z * SEQ + tile_m) * HIDDEN;
    const __half* Al = g_ql + ((size_t)z * SEQ + tile_m) * HIDDEN;
    const __half* Bh = g_kh + ((size_t)z * SEQ + tile_n) * HIDDEN;
    float* C = g_scores + (size_t)z * SEQ * SEQ + (size_t)tile_m * SEQ + tile_n;
    const float scale = 0.04419417382415922f;   // 1/sqrt(512)

    gemm_mma_body(Ah, Al, HIDDEN, Bh, HIDDEN, HIDDEN,
        [&](int r, int c, float v) {
            C[(size_t)r * SEQ + c] = v * scale;
        });
}

// ============================================================
// Kernel 4: row softmax; writes attn fp16 hi/lo
// ============================================================
__global__ void softmax_kernel()
{
    const int row = blockIdx.x;
    const float* p = g_scores + (size_t)row * SEQ;
    __half* oh = g_ah + (size_t)row * SEQ;
    __half* ol = g_al + (size_t)row * SEQ;
    const int t = threadIdx.x;
    __shared__ float red[16];

    float v[8];
    float lmax = -1e30f;
    #pragma unroll
    for (int i = 0; i < 8; i++) {
        v[i] = p[t + i * 256];
        lmax = fmaxf(lmax, v[i]);
    }
    #pragma unroll
    for (int o = 16; o; o >>= 1)
        lmax = fmaxf(lmax, __shfl_xor_sync(0xffffffffu, lmax, o));
    if ((t & 31) == 0) red[t >> 5] = lmax;
    __syncthreads();
    float rmax = red[0];
    #pragma unroll
    for (int i = 1; i < 8; i++) rmax = fmaxf(rmax, red[i]);

    float lsum = 0.0f;
    #pragma unroll
    for (int i = 0; i < 8; i++) {
        v[i] = __expf(v[i] - rmax);
        lsum += v[i];
    }
    #pragma unroll
    for (int o = 16; o; o >>= 1)
        lsum += __shfl_xor_sync(0xffffffffu, lsum, o);
    if ((t & 31) == 0) red[8 + (t >> 5)] = lsum;
    __syncthreads();
    float total = 0.0f;
    #pragma unroll
    for (int i = 0; i < 8; i++) total += red[8 + i];

    float inv = 1.0f / total;
    #pragma unroll
    for (int i = 0; i < 8; i++) {
        float pr = v[i] * inv;
        __half h, l;
        f16_split(pr, h, l);
        oh[t + i * 256] = h;
        ol[t + i * 256] = l;
    }
}

// ============================================================
// Kernel 5: out = attn @ V  (B = V^T hi, K-major over tokens)
// ============================================================
__global__ void __launch_bounds__(256, 2) out_mma_kernel(float* __restrict__ out)
{
    const int z = blockIdx.z;
    const int tile_n = blockIdx.x * 128;   // head dim
    const int tile_m = blockIdx.y * 128;   // query pos
    const __half* Ah = g_ah + (size_t)z * SEQ * SEQ + (size_t)tile_m * SEQ;
    const __half* Al = g_al + (size_t)z * SEQ * SEQ + (size_t)tile_m * SEQ;
    const __half* Bh = g_vth + ((size_t)z * HIDDEN + tile_n) * SEQ;
    float* C = out + ((size_t)z * SEQ + tile_m) * HIDDEN + tile_n;

    gemm_mma_body(Ah, Al, SEQ, Bh, SEQ, SEQ,
        [&](int r, int c, float v) {
            C[(size_t)r * HIDDEN + c] = v;
        });
}

// ============================================================
// launch
// ============================================================
extern "C" void kernel_launch(void* const* d_in, const int* in_sizes, int n_in,
                              void* d_out, int out_size)
{
    const int*   tok = (const int*)  d_in[0];
    const float* emb = (const float*)d_in[1];
    const float* W1  = (const float*)d_in[2];
    const float* b1  = (const float*)d_in[3];
    const float* Wq  = (const float*)d_in[4];
    const float* bq  = (const float*)d_in[5];
    const float* Wk  = (const float*)d_in[6];
    const float* bk  = (const float*)d_in[7];
    const float* Wv  = (const float*)d_in[8];
    const float* bv  = (const float*)d_in[9];
    float* out = (float*)d_out;

    static int smem_set = 0;
    if (!smem_set) {
        (void)cudaFuncSetAttribute(embed_mma_kernel,
                                   cudaFuncAttributeMaxDynamicSharedMemorySize, SMEM_BYTES);
        (void)cudaFuncSetAttribute(qkv_mma_kernel,
                                   cudaFuncAttributeMaxDynamicSharedMemorySize, SMEM_BYTES);
        (void)cudaFuncSetAttribute(scores_mma_kernel,
                                   cudaFuncAttributeMaxDynamicSharedMemorySize, SMEM_BYTES);
        (void)cudaFuncSetAttribute(out_mma_kernel,
                                   cudaFuncAttributeMaxDynamicSharedMemorySize, SMEM_BYTES);
        smem_set = 1;
    }

    dim3 blk(256);
    esplit_kernel<<<dim3(ROWS * EMBED / 256), blk>>>(tok, emb);
    w1split_kernel<<<dim3(HIDDEN * EMBED / 256), blk>>>(W1);
    wsplit_kernel<<<dim3(HIDDEN * HIDDEN / 256, 1, 3), blk>>>(Wq, Wk, Wv);
    embed_mma_kernel<<<dim3(HIDDEN / 128, ROWS / 128), blk, SMEM_BYTES>>>(b1);
    qkv_mma_kernel<<<dim3(HIDDEN / 128, ROWS / 128, 3), blk, SMEM_BYTES>>>(bq, bk, bv);
    scores_mma_kernel<<<dim3(SEQ / 128, SEQ / 128, BATCH), blk, SMEM_BYTES>>>();
    softmax_kernel<<<dim3(ROWS), blk>>>();
    out_mma_kernel<<<dim3(HIDDEN / 128, SEQ / 128, BATCH), blk, SMEM_BYTES>>>(out);
}

// round 17
// speedup vs baseline: 2.2121x; 1.5159x over previous
#include <cuda_runtime.h>
#include <cuda_fp16.h>
#include <math.h>
#include <stdint.h>

#define BATCH  4
#define SEQ    2048
#define EMBED  256
#define HIDDEN 512
#define ROWS   (BATCH * SEQ)   // 8192

// -------- scratch (allocation-free: __device__ globals) --------
__device__ __align__(16) __half g_eh[ROWS * EMBED];                // emb gathered fp16
__device__ __align__(16) __half g_w1h[HIDDEN * EMBED];             // W1^T [n][k]
__device__ __align__(16) __half g_acth[ROWS * HIDDEN];
__device__ __align__(16) __half g_wth[3 * HIDDEN * HIDDEN];        // W^T [z][n][k]
__device__ __align__(16) __half g_qh[ROWS * HIDDEN];
__device__ __align__(16) __half g_kh[ROWS * HIDDEN];
__device__ __align__(16) __half g_vth[BATCH * HIDDEN * SEQ];       // V^T [b][h][s]
__device__ float g_scores[(size_t)BATCH * SEQ * SEQ];              // 64 MB
__device__ __align__(16) __half g_ah[(size_t)BATCH * SEQ * SEQ];   // attn fp16

// ============================================================
// Prep kernels
// ============================================================
__global__ void esplit_kernel(const int* __restrict__ tok,
                              const float* __restrict__ emb)
{
    int idx = blockIdx.x * 256 + threadIdx.x;       // over ROWS*EMBED
    int row = idx >> 8, col = idx & 255;
    int token = tok[row];
    g_eh[idx] = __float2half_rn(emb[(size_t)token * EMBED + col]);
}

__global__ void w1split_kernel(const float* __restrict__ W1)
{
    int idx = blockIdx.x * 256 + threadIdx.x;       // over HIDDEN*EMBED
    int n = idx >> 8, k = idx & 255;
    g_w1h[idx] = __float2half_rn(W1[k * HIDDEN + n]);
}

__global__ void wsplit_kernel(const float* __restrict__ Wq,
                              const float* __restrict__ Wk,
                              const float* __restrict__ Wv)
{
    const int z = blockIdx.z;
    const float* W = (z == 0) ? Wq : (z == 1) ? Wk : Wv;
    int idx = blockIdx.x * 256 + threadIdx.x;       // over 512*512
    int n = idx >> 9, k = idx & 511;
    g_wth[(size_t)z * HIDDEN * HIDDEN + idx] = __float2half_rn(W[k * HIDDEN + n]);
}

// ============================================================
// Warp-MMA GEMM core: single-pass fp16, mma.sync m16n8k16
// f32.f16.f16.f32, 2-stage cp.async pipeline, ldmatrix loads
// with cross-k16-step fragment prefetch.
// C tile 128x128, 8 warps (2m x 4n), warp tile 64x32, KC=32.
// Smem: 2 stages x 2 tiles x [128][40] half = 40960 B.
// ============================================================
#define KC          32
#define SPITCH      40
#define TILE_ELEMS  (128 * SPITCH)
#define STAGE_ELEMS (2 * TILE_ELEMS)
#define SMEM_BYTES  (2 * STAGE_ELEMS * 2)   // 40960

extern __shared__ __half dsm[];

__device__ __forceinline__ uint32_t smem_u32(const void* p) {
    uint32_t a;
    asm("{ .reg .u64 t; cvta.to.shared.u64 t, %1; cvt.u32.u64 %0, t; }" : "=r"(a) : "l"(p));
    return a;
}
__device__ __forceinline__ void cp16(uint32_t dst, const void* src) {
    asm volatile("cp.async.cg.shared.global [%0], [%1], 16;" :: "r"(dst), "l"(src));
}
__device__ __forceinline__ void cp_commit() {
    asm volatile("cp.async.commit_group;" ::: "memory");
}
template <int N>
__device__ __forceinline__ void cp_wait() {
    asm volatile("cp.async.wait_group %0;" :: "n"(N) : "memory");
}

__device__ __forceinline__ void mma16816(float c[4], const uint32_t a[4], const uint32_t b[2]) {
    asm volatile(
        "mma.sync.aligned.m16n8k16.row.col.f32.f16.f16.f32 "
        "{%0,%1,%2,%3}, {%4,%5,%6,%7}, {%8,%9}, {%0,%1,%2,%3};"
        : "+f"(c[0]), "+f"(c[1]), "+f"(c[2]), "+f"(c[3])
        : "r"(a[0]), "r"(a[1]), "r"(a[2]), "r"(a[3]), "r"(b[0]), "r"(b[1]));
}

__device__ __forceinline__ void ldsm4(uint32_t r[4], uint32_t addr) {
    asm volatile("ldmatrix.sync.aligned.m8n8.x4.shared.b16 {%0,%1,%2,%3}, [%4];"
                 : "=r"(r[0]), "=r"(r[1]), "=r"(r[2]), "=r"(r[3]) : "r"(addr));
}

__device__ __forceinline__ void load_afrag(uint32_t base, int kk, int wm,
                                           uint32_t a_off, uint32_t f[4][4]) {
    #pragma unroll
    for (int mi = 0; mi < 4; mi++) {
        uint32_t ro = (uint32_t)((wm + mi * 16) * SPITCH + kk) * 2;
        ldsm4(f[mi], base + a_off + ro);
    }
}
__device__ __forceinline__ void load_bfrag(uint32_t base, int kk, int wn,
                                           uint32_t b_off, uint32_t f[4][2]) {
    #pragma unroll
    for (int np = 0; np < 2; np++) {
        uint32_t ro = (uint32_t)((wn + np * 16) * SPITCH + kk) * 2;
        uint32_t r[4];
        ldsm4(r, base + b_off + ro);
        f[np * 2][0] = r[0]; f[np * 2][1] = r[1];
        f[np * 2 + 1][0] = r[2]; f[np * 2 + 1][1] = r[3];
    }
}

// async copy of one 128x32 half tile into padded smem tile
__device__ __forceinline__ void copy_tile_async(const __half* __restrict__ src,
                                                size_t ld, uint32_t dst, int t)
{
    #pragma unroll
    for (int i = 0; i < 2; i++) {
        int idx = t + i * 256;
        int r = idx >> 2, c = idx & 3;
        cp16(dst + (uint32_t)(r * SPITCH + c * 8) * 2,
             src + (size_t)r * ld + c * 8);
    }
}

template <class Epi>
__device__ __forceinline__ void gemm_mma_body(
    const __half* __restrict__ A, size_t lda,
    const __half* __restrict__ B, size_t ldb,
    int K, Epi epi)
{
    const int t    = threadIdx.x;
    const int lane = t & 31;
    const int wid  = t >> 5;
    const int wm   = (wid & 1) * 64;      // warp m-offset
    const int wn   = (wid >> 1) * 32;     // warp n-offset
    const int g    = lane >> 2;
    const int tg   = lane & 3;

    const int lr = lane & 7, q = lane >> 3;
    const uint32_t a_off = (uint32_t)(((lr + (q & 1) * 8) * SPITCH) + (q & 2) * 4) * 2;
    const uint32_t b_off = (uint32_t)(((lr + (q & 2) * 4) * SPITCH) + (q & 1) * 8) * 2;

    const uint32_t sbase = smem_u32(dsm);
    const int kTiles = K / KC;

    float acc[4][4][4] = {};

    // prologue: prefetch stage 0 (2 tiles)
    {
        uint32_t st = sbase;
        copy_tile_async(A, lda, st,                  t);
        copy_tile_async(B, ldb, st + TILE_ELEMS * 2, t);
        cp_commit();
    }

    int s = 0;
    for (int kb = 0; kb < kTiles; kb++) {
        if (kb + 1 < kTiles) {
            const size_t ko = (size_t)(kb + 1) * KC;
            uint32_t st = sbase + (uint32_t)((s ^ 1) * STAGE_ELEMS) * 2;
            copy_tile_async(A + ko, lda, st,                  t);
            copy_tile_async(B + ko, ldb, st + TILE_ELEMS * 2, t);
            cp_commit();
            cp_wait<1>();
        } else {
            cp_wait<0>();
        }
        __syncthreads();

        const uint32_t stb = sbase + (uint32_t)(s * STAGE_ELEMS) * 2;
        const uint32_t aB = stb;
        const uint32_t bB = stb + TILE_ELEMS * 2;

        uint32_t a0[4][4], b0[4][2], a1[4][4], b1[4][2];

        // ---- serial head (once per stage): fragments for kk=0 ----
        load_afrag(aB, 0, wm, a_off, a0);
        load_bfrag(bB, 0, wn, b_off, b0);

        // kk = 0 : first half, then prefetch kk=16 under MMA cover
        #pragma unroll
        for (int mi = 0; mi < 2; mi++)
            #pragma unroll
            for (int ni = 0; ni < 4; ni++)
                mma16816(acc[mi][ni], a0[mi], b0[ni]);
        load_afrag(aB, 16, wm, a_off, a1);
        load_bfrag(bB, 16, wn, b_off, b1);
        #pragma unroll
        for (int mi = 2; mi < 4; mi++)
            #pragma unroll
            for (int ni = 0; ni < 4; ni++)
                mma16816(acc[mi][ni], a0[mi], b0[ni]);

        // kk = 16
        #pragma unroll
        for (int mi = 0; mi < 4; mi++)
            #pragma unroll
            for (int ni = 0; ni < 4; ni++)
                mma16816(acc[mi][ni], a1[mi], b1[ni]);

        __syncthreads();
        s ^= 1;
    }

    #pragma unroll
    for (int mi = 0; mi < 4; mi++)
        #pragma unroll
        for (int ni = 0; ni < 4; ni++) {
            int r0 = wm + mi * 16 + g;
            int c0 = wn + ni * 8 + tg * 2;
            epi(r0,     c0,     acc[mi][ni][0]);
            epi(r0,     c0 + 1, acc[mi][ni][1]);
            epi(r0 + 8, c0,     acc[mi][ni][2]);
            epi(r0 + 8, c0 + 1, acc[mi][ni][3]);
        }
}

// ============================================================
// Kernel 1: act = gelu( emb @ W1 + b1 )
// ============================================================
__global__ void __launch_bounds__(256, 2) embed_mma_kernel(const float* __restrict__ b1)
{
    const int tile_n = blockIdx.x * 128;
    const int tile_m = blockIdx.y * 128;
    const __half* A = g_eh + (size_t)tile_m * EMBED;
    const __half* B = g_w1h + (size_t)tile_n * EMBED;

    gemm_mma_body(A, EMBED, B, EMBED, EMBED,
        [&](int r, int c, float v) {
            int row = tile_m + r, col = tile_n + c;
            float x = v + b1[col];
            float gl = 0.5f * x * (1.0f + erff(x * 0.7071067811865475f));
            g_acth[(size_t)row * HIDDEN + col] = __float2half_rn(gl);
        });
}

// ============================================================
// Kernel 2: q/k/v = act @ W + b  (v stored transposed)
// ============================================================
__global__ void __launch_bounds__(256, 2) qkv_mma_kernel(const float* __restrict__ bq,
                                                         const float* __restrict__ bk,
                                                         const float* __restrict__ bv)
{
    const int z = blockIdx.z;
    const int tile_n = blockIdx.x * 128;
    const int tile_m = blockIdx.y * 128;
    const float* bias = (z == 0) ? bq : (z == 1) ? bk : bv;

    const __half* A = g_acth + (size_t)tile_m * HIDDEN;
    const __half* B = g_wth + (size_t)z * HIDDEN * HIDDEN + (size_t)tile_n * HIDDEN;

    gemm_mma_body(A, HIDDEN, B, HIDDEN, HIDDEN,
        [&](int r, int c, float v) {
            int row = tile_m + r, col = tile_n + c;
            __half x = __float2half_rn(v + bias[col]);
            if (z == 0) {
                g_qh[(size_t)row * HIDDEN + col] = x;
            } else if (z == 1) {
                g_kh[(size_t)row * HIDDEN + col] = x;
            } else {
                int b = row >> 11, sq = row & (SEQ - 1);
                g_vth[((size_t)b * HIDDEN + col) * SEQ + sq] = x;
            }
        });
}

// ============================================================
// Kernel 3: scores = (Q @ K^T) / sqrt(512)
// ============================================================
__global__ void __launch_bounds__(256, 2) scores_mma_kernel()
{
    const int z = blockIdx.z;
    const int tile_n = blockIdx.x * 128;
    const int tile_m = blockIdx.y * 128;
    const __half* A = g_qh + ((size_t)z * SEQ + tile_m) * HIDDEN;
    const __half* B = g_kh + ((size_t)z * SEQ + tile_n) * HIDDEN;
    float* C = g_scores + (size_t)z * SEQ * SEQ + (size_t)tile_m * SEQ + tile_n;
    const float scale = 0.04419417382415922f;   // 1/sqrt(512)

    gemm_mma_body(A, HIDDEN, B, HIDDEN, HIDDEN,
        [&](int r, int c, float v) {
            C[(size_t)r * SEQ + c] = v * scale;
        });
}

// ============================================================
// Kernel 4: row softmax; writes attn fp16
// ============================================================
__global__ void softmax_kernel()
{
    const int row = blockIdx.x;
    const float* p = g_scores + (size_t)row * SEQ;
    __half* oh = g_ah + (size_t)row * SEQ;
    const int t = threadIdx.x;
    __shared__ float red[16];

    float v[8];
    float lmax = -1e30f;
    #pragma unroll
    for (int i = 0; i < 8; i++) {
        v[i] = p[t + i * 256];
        lmax = fmaxf(lmax, v[i]);
    }
    #pragma unroll
    for (int o = 16; o; o >>= 1)
        lmax = fmaxf(lmax, __shfl_xor_sync(0xffffffffu, lmax, o));
    if ((t & 31) == 0) red[t >> 5] = lmax;
    __syncthreads();
    float rmax = red[0];
    #pragma unroll
    for (int i = 1; i < 8; i++) rmax = fmaxf(rmax, red[i]);

    float lsum = 0.0f;
    #pragma unroll
    for (int i = 0; i < 8; i++) {
        v[i] = __expf(v[i] - rmax);
        lsum += v[i];
    }
    #pragma unroll
    for (int o = 16; o; o >>= 1)
        lsum += __shfl_xor_sync(0xffffffffu, lsum, o);
    if ((t & 31) == 0) red[8 + (t >> 5)] = lsum;
    __syncthreads();
    float total = 0.0f;
    #pragma unroll
    for (int i = 0; i < 8; i++) total += red[8 + i];

    float inv = 1.0f / total;
    #pragma unroll
    for (int i = 0; i < 8; i++)
        oh[t + i * 256] = __float2half_rn(v[i] * inv);
}

// ============================================================
// Kernel 5: out = attn @ V  (B = V^T, K-major over tokens)
// ============================================================
__global__ void __launch_bounds__(256, 2) out_mma_kernel(float* __restrict__ out)
{
    const int z = blockIdx.z;
    const int tile_n = blockIdx.x * 128;   // head dim
    const int tile_m = blockIdx.y * 128;   // query pos
    const __half* A = g_ah + (size_t)z * SEQ * SEQ + (size_t)tile_m * SEQ;
    const __half* B = g_vth + ((size_t)z * HIDDEN + tile_n) * SEQ;
    float* C = out + ((size_t)z * SEQ + tile_m) * HIDDEN + tile_n;

    gemm_mma_body(A, SEQ, B, SEQ, SEQ,
        [&](int r, int c, float v) {
            C[(size_t)r * HIDDEN + c] = v;
        });
}

// ============================================================
// launch
// ============================================================
extern "C" void kernel_launch(void* const* d_in, const int* in_sizes, int n_in,
                              void* d_out, int out_size)
{
    const int*   tok = (const int*)  d_in[0];
    const float* emb = (const float*)d_in[1];
    const float* W1  = (const float*)d_in[2];
    const float* b1  = (const float*)d_in[3];
    const float* Wq  = (const float*)d_in[4];
    const float* bq  = (const float*)d_in[5];
    const float* Wk  = (const float*)d_in[6];
    const float* bk  = (const float*)d_in[7];
    const float* Wv  = (const float*)d_in[8];
    const float* bv  = (const float*)d_in[9];
    float* out = (float*)d_out;

    static int smem_set = 0;
    if (!smem_set) {
        (void)cudaFuncSetAttribute(embed_mma_kernel,
                                   cudaFuncAttributeMaxDynamicSharedMemorySize, SMEM_BYTES);
        (void)cudaFuncSetAttribute(qkv_mma_kernel,
                                   cudaFuncAttributeMaxDynamicSharedMemorySize, SMEM_BYTES);
        (void)cudaFuncSetAttribute(scores_mma_kernel,
                                   cudaFuncAttributeMaxDynamicSharedMemorySize, SMEM_BYTES);
        (void)cudaFuncSetAttribute(out_mma_kernel,
                                   cudaFuncAttributeMaxDynamicSharedMemorySize, SMEM_BYTES);
        smem_set = 1;
    }

    dim3 blk(256);
    esplit_kernel<<<dim3(ROWS * EMBED / 256), blk>>>(tok, emb);
    w1split_kernel<<<dim3(HIDDEN * EMBED / 256), blk>>>(W1);
    wsplit_kernel<<<dim3(HIDDEN * HIDDEN / 256, 1, 3), blk>>>(Wq, Wk, Wv);
    embed_mma_kernel<<<dim3(HIDDEN / 128, ROWS / 128), blk, SMEM_BYTES>>>(b1);
    qkv_mma_kernel<<<dim3(HIDDEN / 128, ROWS / 128, 3), blk, SMEM_BYTES>>>(bq, bk, bv);
    scores_mma_kernel<<<dim3(SEQ / 128, SEQ / 128, BATCH), blk, SMEM_BYTES>>>();
    softmax_kernel<<<dim3(ROWS), blk>>>();
    out_mma_kernel<<<dim3(HIDDEN / 128, SEQ / 128, BATCH), blk, SMEM_BYTES>>>(out);
}